// round 1
// baseline (speedup 1.0000x reference)
#include <cuda_runtime.h>
#include <math.h>

#define D 128
#define NPB 64          // nodes per block in MLP kernel
#define MAXN 100000
#define MAXG 512

// ---------------- scratch (no allocations allowed) ----------------
__device__ float g_hA[MAXN * D];
__device__ float g_hB[MAXN * D];
__device__ float g_agg[MAXN * D];
__device__ float g_stats[2 * D];          // [0:D) sum, [D:2D) sumsq
__device__ float g_bnscale[D];
__device__ float g_bnshift[D];
__device__ float g_psum[MAXG * D];
__device__ int   g_pmax[MAXG * D];        // float bits; values are >=0 post-ReLU
__device__ int   g_pcnt[MAXG];

// ---------------- edge scatter: one warp per edge, vector red ----------------
__global__ void scatter_kernel(const float* __restrict__ h,
                               const int* __restrict__ src,
                               const int* __restrict__ dst,
                               float* __restrict__ agg, int nE)
{
    int warp = (blockIdx.x * blockDim.x + threadIdx.x) >> 5;
    int lane = threadIdx.x & 31;
    if (warp >= nE) return;
    int s = src[warp];
    int d = dst[warp];
    float4 v = reinterpret_cast<const float4*>(h + (size_t)s * D)[lane];
    float* p = agg + (size_t)d * D + lane * 4;
    asm volatile("red.global.add.v4.f32 [%0], {%1,%2,%3,%4};"
                 :: "l"(p), "f"(v.x), "f"(v.y), "f"(v.z), "f"(v.w)
                 : "memory");
}

// ---------------- fused GIN MLP: relu(z@W1+b1)@W2+b2, relu, + BN partial stats -----
// block = 128 threads (thread j owns output feature j, weight column in registers)
__global__ __launch_bounds__(128) void mlp_kernel(
    const float* __restrict__ h, const float* __restrict__ agg,
    const float* __restrict__ W1, const float* __restrict__ b1,
    const float* __restrict__ W2, const float* __restrict__ b2,
    float* __restrict__ hout, float* __restrict__ stats, int do_stats, int n)
{
    __shared__ float s_t[NPB * D];
    __shared__ float s_z[D];
    int j = threadIdx.x;
    int base = blockIdx.x * NPB;
    int cnt = n - base;
    if (cnt > NPB) cnt = NPB;

    float w[D];
#pragma unroll
    for (int k = 0; k < D; k++) w[k] = W1[k * D + j];
    float bb = b1[j];

    for (int i = 0; i < cnt; i++) {
        size_t off = (size_t)(base + i) * D;
        __syncthreads();
        s_z[j] = h[off + j] + agg[off + j];
        __syncthreads();
        float acc = bb;
#pragma unroll
        for (int k = 0; k < D; k++) acc = fmaf(s_z[k], w[k], acc);
        s_t[i * D + j] = fmaxf(acc, 0.f);
    }

#pragma unroll
    for (int k = 0; k < D; k++) w[k] = W2[k * D + j];
    bb = b2[j];
    __syncthreads();

    float lsum = 0.f, lsq = 0.f;
    for (int i = 0; i < cnt; i++) {
        float acc = bb;
#pragma unroll
        for (int k = 0; k < D; k++) acc = fmaf(s_t[i * D + k], w[k], acc);
        acc = fmaxf(acc, 0.f);
        hout[(size_t)(base + i) * D + j] = acc;
        lsum += acc;
        lsq += acc * acc;
    }
    if (do_stats) {
        atomicAdd(&stats[j], lsum);
        atomicAdd(&stats[D + j], lsq);
    }
}

// ---------------- batch-norm: fold stats into scale/shift, then apply ----------------
__global__ void bn_scale_kernel(const float* __restrict__ stats,
                                const float* __restrict__ gamma,
                                const float* __restrict__ beta, float inv_n)
{
    int j = threadIdx.x;
    float mu = stats[j] * inv_n;
    float var = stats[D + j] * inv_n - mu * mu;
    float sc = gamma[j] * rsqrtf(var + 1e-5f);
    g_bnscale[j] = sc;
    g_bnshift[j] = beta[j] - mu * sc;
}

__global__ void bn_apply_kernel(float* __restrict__ h, int n4)
{
    int i = blockIdx.x * blockDim.x + threadIdx.x;
    if (i >= n4) return;
    float4 v = reinterpret_cast<float4*>(h)[i];
    int j = (i & 31) * 4;
    v.x = fmaf(v.x, g_bnscale[j + 0], g_bnshift[j + 0]);
    v.y = fmaf(v.y, g_bnscale[j + 1], g_bnshift[j + 1]);
    v.z = fmaf(v.z, g_bnscale[j + 2], g_bnshift[j + 2]);
    v.w = fmaf(v.w, g_bnscale[j + 3], g_bnshift[j + 3]);
    reinterpret_cast<float4*>(h)[i] = v;
}

// ---------------- per-graph mean/max pooling ----------------
__global__ void pool_kernel(const float* __restrict__ h,
                            const int* __restrict__ batch, int total)
{
    int gid = blockIdx.x * blockDim.x + threadIdx.x;
    if (gid >= total) return;
    int node = gid >> 7;
    int j = gid & 127;
    int b = batch[node];
    float v = h[gid];
    atomicAdd(&g_psum[b * D + j], v);
    atomicMax(&g_pmax[b * D + j], __float_as_int(v));  // v >= 0 -> int-order == float-order
    if (j == 0) atomicAdd(&g_pcnt[b], 1);
}

// ---------------- final graph head: [mean|max]@Wg+bg, cosine scores, loss sum ------
__device__ __forceinline__ float breduce128(float v, float* s4)
{
    int lane = threadIdx.x & 31, w = threadIdx.x >> 5;
#pragma unroll
    for (int o = 16; o; o >>= 1) v += __shfl_down_sync(0xffffffffu, v, o);
    if (lane == 0) s4[w] = v;
    __syncthreads();
    float r = s4[0] + s4[1] + s4[2] + s4[3];
    __syncthreads();
    return r;
}

__global__ __launch_bounds__(128) void final_kernel(
    const float* __restrict__ psum, const int* __restrict__ pmax,
    const int* __restrict__ pcnt,
    const float* __restrict__ Wg, const float* __restrict__ bg,
    const float* __restrict__ pb, const float* __restrict__ pm,
    const int* __restrict__ y, float* __restrict__ out)
{
    __shared__ float s_gx[2 * D];
    __shared__ float s4[4];
    int g = blockIdx.x, j = threadIdx.x;

    float cntf = fmaxf((float)pcnt[g], 1.f);
    s_gx[j]     = psum[g * D + j] / cntf;
    s_gx[D + j] = __int_as_float(pmax[g * D + j]);
    __syncthreads();

    float rep = bg[j];
#pragma unroll
    for (int k = 0; k < 2 * D; k++) rep = fmaf(s_gx[k], Wg[k * D + j], rep);

    float nrm = breduce128(rep * rep, s4);
    float feat = rep / fmaxf(sqrtf(nrm), 1e-12f);

    float pbj = pb[j], pmj = pm[j];
    float nb = breduce128(pbj * pbj, s4);
    float nm = breduce128(pmj * pmj, s4);
    pbj /= fmaxf(sqrtf(nb), 1e-12f);
    pmj /= fmaxf(sqrtf(nm), 1e-12f);

    float cb = breduce128(feat * pbj, s4);
    float cm = breduce128(feat * pmj, s4);

    if (j == 0) {
        bool mal = (y[g] == 1);
        float a = mal ? cb * cb : (1.f - cb) * (1.f - cb);
        float b = mal ? (1.f - cm) * (1.f - cm) : cm * cm;
        atomicAdd(out, a + b);
    }
}

// ---------------- host ----------------
extern "C" void kernel_launch(void* const* d_in, const int* in_sizes, int n_in,
                              void* d_out, int out_size)
{
    const float* x   = (const float*)d_in[0];
    const int* ei    = (const int*)d_in[1];
    const int* batch = (const int*)d_in[2];
    const int* y     = (const int*)d_in[3];
    const float* W1  = (const float*)d_in[4];
    const float* b1  = (const float*)d_in[5];
    const float* W2  = (const float*)d_in[6];
    const float* b2  = (const float*)d_in[7];
    const float* bng = (const float*)d_in[8];
    const float* bnb = (const float*)d_in[9];
    const float* Wg  = (const float*)d_in[10];
    const float* bg  = (const float*)d_in[11];
    const float* pb  = (const float*)d_in[12];
    const float* pm  = (const float*)d_in[13];

    int n  = in_sizes[0] / D;
    int nE = in_sizes[1] / 2;
    int G  = in_sizes[3];
    const int* src = ei;
    const int* dst = ei + nE;

    float *hA, *hB, *agg, *stats;
    void *psum, *pmax, *pcnt;
    cudaGetSymbolAddress((void**)&hA, g_hA);
    cudaGetSymbolAddress((void**)&hB, g_hB);
    cudaGetSymbolAddress((void**)&agg, g_agg);
    cudaGetSymbolAddress((void**)&stats, g_stats);
    cudaGetSymbolAddress(&psum, g_psum);
    cudaGetSymbolAddress(&pmax, g_pmax);
    cudaGetSymbolAddress(&pcnt, g_pcnt);

    const float* cur = x;
    float* nxt = hA;
    int mlpBlocks  = (n + NPB - 1) / NPB;
    long long scatThreads = (long long)nE * 32;
    int scatBlocks = (int)((scatThreads + 255) / 256);

    for (int l = 0; l < 3; l++) {
        cudaMemsetAsync(agg, 0, (size_t)n * D * sizeof(float));
        scatter_kernel<<<scatBlocks, 256>>>(cur, src, dst, agg, nE);
        int do_stats = (l < 2);
        if (do_stats) cudaMemsetAsync(stats, 0, 2 * D * sizeof(float));
        mlp_kernel<<<mlpBlocks, 128>>>(cur, agg,
                                       W1 + l * D * D, b1 + l * D,
                                       W2 + l * D * D, b2 + l * D,
                                       nxt, stats, do_stats, n);
        if (do_stats) {
            bn_scale_kernel<<<1, D>>>(stats, bng + l * D, bnb + l * D, 1.f / (float)n);
            int n4 = n * D / 4;
            bn_apply_kernel<<<(n4 + 255) / 256, 256>>>(nxt, n4);
        }
        cur = nxt;
        nxt = (l == 0) ? hB : hA;
    }

    cudaMemsetAsync(psum, 0, (size_t)G * D * sizeof(float));
    cudaMemsetAsync(pmax, 0, (size_t)G * D * sizeof(int));
    cudaMemsetAsync(pcnt, 0, (size_t)G * sizeof(int));
    int total = n * D;
    pool_kernel<<<(total + 255) / 256, 256>>>(cur, batch, total);

    cudaMemsetAsync(d_out, 0, sizeof(float));
    final_kernel<<<G, 128>>>((const float*)psum, (const int*)pmax, (const int*)pcnt,
                             Wg, bg, pb, pm, y, (float*)d_out);
}

// round 3
// speedup vs baseline: 1.3020x; 1.3020x over previous
#include <cuda_runtime.h>
#include <math.h>

#define D 128
#define NPB 64
#define MAXN 100000
#define MAXE 1600000
#define MAXG 512

// ---------------- scratch ----------------
__device__ float g_hA[MAXN * D];
__device__ float g_hB[MAXN * D];
__device__ float g_z[MAXN * D];
__device__ int   g_rowptr[MAXN + 1];
__device__ int   g_cursor[MAXN + 1];      // also deg histogram
__device__ int   g_partial[256];
__device__ int   g_csrsrc[MAXE];
__device__ float g_stats[2 * D];
__device__ float g_bnscale[D];
__device__ float g_bnshift[D];
__device__ float g_psum[MAXG * D];
__device__ int   g_pmax[MAXG * D];
__device__ int   g_pcnt[MAXG];

// ================= CSR build =================
__global__ void hist_kernel(const int* __restrict__ dst, int* __restrict__ deg, int nE)
{
    int e = blockIdx.x * blockDim.x + threadIdx.x;
    if (e < nE) atomicAdd(&deg[dst[e]], 1);
}

#define SCAN_B 1024
__global__ void scan1_kernel(const int* __restrict__ deg, int* __restrict__ rowptr,
                             int* __restrict__ partial, int n)
{
    __shared__ int sh[SCAN_B];
    int i = blockIdx.x * SCAN_B + threadIdx.x;
    int v = (i < n) ? deg[i] : 0;
    sh[threadIdx.x] = v;
    __syncthreads();
    for (int o = 1; o < SCAN_B; o <<= 1) {
        int t = (threadIdx.x >= o) ? sh[threadIdx.x - o] : 0;
        __syncthreads();
        sh[threadIdx.x] += t;
        __syncthreads();
    }
    if (i < n) rowptr[i] = sh[threadIdx.x] - v;      // exclusive
    if (threadIdx.x == SCAN_B - 1) partial[blockIdx.x] = sh[SCAN_B - 1];
}

__global__ void scan2_kernel(int* __restrict__ partial, int nb)
{
    if (threadIdx.x == 0) {
        int acc = 0;
        for (int i = 0; i < nb; i++) { int t = partial[i]; partial[i] = acc; acc += t; }
        partial[nb] = acc;
    }
}

__global__ void scan3_kernel(int* __restrict__ rowptr, const int* __restrict__ partial,
                             int n, int nb)
{
    int i = blockIdx.x * SCAN_B + threadIdx.x;
    if (i < n) rowptr[i] += partial[blockIdx.x];
    if (i == 0) rowptr[n] = partial[nb];
}

__global__ void fill_kernel(const int* __restrict__ src, const int* __restrict__ dst,
                            int* __restrict__ cursor, int* __restrict__ csrsrc, int nE)
{
    int e = blockIdx.x * blockDim.x + threadIdx.x;
    if (e >= nE) return;
    int p = atomicAdd(&cursor[dst[e]], 1);
    csrsrc[p] = src[e];
}

// ================= gather (+ optional fused BN of the PREVIOUS layer) =============
// z_i = s * (h_i + sum_j h_j) + t * (1 + deg_i)   [s=1,t=0 when apply_bn=0]
__global__ void gather_kernel(const float* __restrict__ h,
                              const int* __restrict__ rowptr,
                              const int* __restrict__ csrsrc,
                              float* __restrict__ z, int n, int apply_bn)
{
    int node = (blockIdx.x * blockDim.x + threadIdx.x) >> 5;
    int lane = threadIdx.x & 31;
    if (node >= n) return;
    int beg = rowptr[node], end = rowptr[node + 1];
    const float4* h4 = reinterpret_cast<const float4*>(h);
    float4 acc = h4[(size_t)node * 32 + lane];
    for (int e0 = beg; e0 < end; e0 += 32) {
        int myE = e0 + lane;
        int s = (myE < end) ? csrsrc[myE] : 0;
        int cnt = end - e0; if (cnt > 32) cnt = 32;
        for (int j = 0; j < cnt; j++) {
            int sj = __shfl_sync(0xffffffffu, s, j);
            float4 v = h4[(size_t)sj * 32 + lane];
            acc.x += v.x; acc.y += v.y; acc.z += v.z; acc.w += v.w;
        }
    }
    if (apply_bn) {
        float m = (float)(1 + end - beg);
        int j = lane * 4;
        acc.x = fmaf(acc.x, g_bnscale[j + 0], m * g_bnshift[j + 0]);
        acc.y = fmaf(acc.y, g_bnscale[j + 1], m * g_bnshift[j + 1]);
        acc.z = fmaf(acc.z, g_bnscale[j + 2], m * g_bnshift[j + 2]);
        acc.w = fmaf(acc.w, g_bnscale[j + 3], m * g_bnshift[j + 3]);
    }
    reinterpret_cast<float4*>(z)[(size_t)node * 32 + lane] = acc;
}

// ================= fused GIN MLP =================
__global__ __launch_bounds__(128) void mlp_kernel(
    const float* __restrict__ z,
    const float* __restrict__ W1, const float* __restrict__ b1,
    const float* __restrict__ W2, const float* __restrict__ b2,
    float* __restrict__ hout, float* __restrict__ stats, int do_stats, int n)
{
    __shared__ float s_t[NPB * D];
    __shared__ float s_z[D];
    int j = threadIdx.x;
    int base = blockIdx.x * NPB;
    int cnt = n - base;
    if (cnt > NPB) cnt = NPB;

    float w[D];
#pragma unroll
    for (int k = 0; k < D; k++) w[k] = W1[k * D + j];
    float bb = b1[j];

    for (int i = 0; i < cnt; i++) {
        size_t off = (size_t)(base + i) * D;
        __syncthreads();
        s_z[j] = z[off + j];
        __syncthreads();
        float acc = bb;
        const float4* z4 = reinterpret_cast<const float4*>(s_z);
#pragma unroll
        for (int k4 = 0; k4 < 32; k4++) {
            float4 zz = z4[k4];
            acc = fmaf(zz.x, w[4 * k4 + 0], acc);
            acc = fmaf(zz.y, w[4 * k4 + 1], acc);
            acc = fmaf(zz.z, w[4 * k4 + 2], acc);
            acc = fmaf(zz.w, w[4 * k4 + 3], acc);
        }
        s_t[i * D + j] = fmaxf(acc, 0.f);
    }

#pragma unroll
    for (int k = 0; k < D; k++) w[k] = W2[k * D + j];
    bb = b2[j];
    __syncthreads();

    float lsum = 0.f, lsq = 0.f;
    for (int i = 0; i < cnt; i++) {
        float acc = bb;
        const float4* t4 = reinterpret_cast<const float4*>(s_t + i * D);
#pragma unroll
        for (int k4 = 0; k4 < 32; k4++) {
            float4 tt = t4[k4];
            acc = fmaf(tt.x, w[4 * k4 + 0], acc);
            acc = fmaf(tt.y, w[4 * k4 + 1], acc);
            acc = fmaf(tt.z, w[4 * k4 + 2], acc);
            acc = fmaf(tt.w, w[4 * k4 + 3], acc);
        }
        acc = fmaxf(acc, 0.f);
        hout[(size_t)(base + i) * D + j] = acc;
        lsum += acc;
        lsq += acc * acc;
    }
    if (do_stats) {
        atomicAdd(&stats[j], lsum);
        atomicAdd(&stats[D + j], lsq);
    }
}

// ================= BN: fold stats into scale/shift only (apply fused in gather) ===
__global__ void bn_scale_kernel(const float* __restrict__ stats,
                                const float* __restrict__ gamma,
                                const float* __restrict__ beta, float inv_n)
{
    int j = threadIdx.x;
    float mu = stats[j] * inv_n;
    float var = stats[D + j] * inv_n - mu * mu;
    float sc = gamma[j] * rsqrtf(var + 1e-5f);
    g_bnscale[j] = sc;
    g_bnshift[j] = beta[j] - mu * sc;
}

// ================= pooling =================
__global__ void pool_kernel(const float* __restrict__ h,
                            const int* __restrict__ batch, int total)
{
    int gid = blockIdx.x * blockDim.x + threadIdx.x;
    if (gid >= total) return;
    int node = gid >> 7;
    int j = gid & 127;
    int b = batch[node];
    float v = h[gid];
    atomicAdd(&g_psum[b * D + j], v);
    atomicMax(&g_pmax[b * D + j], __float_as_int(v));  // v >= 0 post-ReLU
    if (j == 0) atomicAdd(&g_pcnt[b], 1);
}

// ================= final head =================
__device__ __forceinline__ float breduce128(float v, float* s4)
{
    int lane = threadIdx.x & 31, w = threadIdx.x >> 5;
#pragma unroll
    for (int o = 16; o; o >>= 1) v += __shfl_down_sync(0xffffffffu, v, o);
    if (lane == 0) s4[w] = v;
    __syncthreads();
    float r = s4[0] + s4[1] + s4[2] + s4[3];
    __syncthreads();
    return r;
}

__global__ __launch_bounds__(128) void final_kernel(
    const float* __restrict__ psum, const int* __restrict__ pmax,
    const int* __restrict__ pcnt,
    const float* __restrict__ Wg, const float* __restrict__ bg,
    const float* __restrict__ pb, const float* __restrict__ pm,
    const int* __restrict__ y, float* __restrict__ out)
{
    __shared__ float s_gx[2 * D];
    __shared__ float s4[4];
    int g = blockIdx.x, j = threadIdx.x;

    float cntf = fmaxf((float)pcnt[g], 1.f);
    s_gx[j]     = psum[g * D + j] / cntf;
    s_gx[D + j] = __int_as_float(pmax[g * D + j]);
    __syncthreads();

    float rep = bg[j];
#pragma unroll
    for (int k = 0; k < 2 * D; k++) rep = fmaf(s_gx[k], Wg[k * D + j], rep);

    float nrm = breduce128(rep * rep, s4);
    float feat = rep / fmaxf(sqrtf(nrm), 1e-12f);

    float pbj = pb[j], pmj = pm[j];
    float nb = breduce128(pbj * pbj, s4);
    float nm = breduce128(pmj * pmj, s4);
    pbj /= fmaxf(sqrtf(nb), 1e-12f);
    pmj /= fmaxf(sqrtf(nm), 1e-12f);

    float cb = breduce128(feat * pbj, s4);
    float cm = breduce128(feat * pmj, s4);

    if (j == 0) {
        bool mal = (y[g] == 1);
        float a = mal ? cb * cb : (1.f - cb) * (1.f - cb);
        float b = mal ? (1.f - cm) * (1.f - cm) : cm * cm;
        atomicAdd(out, a + b);
    }
}

// ================= host =================
extern "C" void kernel_launch(void* const* d_in, const int* in_sizes, int n_in,
                              void* d_out, int out_size)
{
    const float* x   = (const float*)d_in[0];
    const int* ei    = (const int*)d_in[1];
    const int* batch = (const int*)d_in[2];
    const int* y     = (const int*)d_in[3];
    const float* W1  = (const float*)d_in[4];
    const float* b1  = (const float*)d_in[5];
    const float* W2  = (const float*)d_in[6];
    const float* b2  = (const float*)d_in[7];
    const float* bng = (const float*)d_in[8];
    const float* bnb = (const float*)d_in[9];
    const float* Wg  = (const float*)d_in[10];
    const float* bg  = (const float*)d_in[11];
    const float* pb  = (const float*)d_in[12];
    const float* pm  = (const float*)d_in[13];

    int n  = in_sizes[0] / D;
    int nE = in_sizes[1] / 2;
    int G  = in_sizes[3];
    const int* src = ei;
    const int* dst = ei + nE;

    float *hA, *hB, *zb, *stats;
    int *rowptr, *cursor, *partial, *csrsrc;
    void *psum, *pmax, *pcnt;
    cudaGetSymbolAddress((void**)&hA, g_hA);
    cudaGetSymbolAddress((void**)&hB, g_hB);
    cudaGetSymbolAddress((void**)&zb, g_z);
    cudaGetSymbolAddress((void**)&stats, g_stats);
    cudaGetSymbolAddress((void**)&rowptr, g_rowptr);
    cudaGetSymbolAddress((void**)&cursor, g_cursor);
    cudaGetSymbolAddress((void**)&partial, g_partial);
    cudaGetSymbolAddress((void**)&csrsrc, g_csrsrc);
    cudaGetSymbolAddress(&psum, g_psum);
    cudaGetSymbolAddress(&pmax, g_pmax);
    cudaGetSymbolAddress(&pcnt, g_pcnt);

    // ---- CSR build (once) ----
    int nb = (n + SCAN_B - 1) / SCAN_B;
    cudaMemsetAsync(cursor, 0, (n + 1) * sizeof(int));     // cursor = deg histogram
    hist_kernel<<<(nE + 255) / 256, 256>>>(dst, cursor, nE);
    scan1_kernel<<<nb, SCAN_B>>>(cursor, rowptr, partial, n);
    scan2_kernel<<<1, 32>>>(partial, nb);
    scan3_kernel<<<nb, SCAN_B>>>(rowptr, partial, n, nb);
    cudaMemcpyAsync(cursor, rowptr, n * sizeof(int), cudaMemcpyDeviceToDevice);
    fill_kernel<<<(nE + 255) / 256, 256>>>(src, dst, cursor, csrsrc, nE);

    // ---- layers ----
    const float* cur = x;
    float* nxt = hA;
    int mlpBlocks = (n + NPB - 1) / NPB;
    int gthBlocks = (n * 32 + 255) / 256;

    for (int l = 0; l < 3; l++) {
        // gather applies the BN of layer l-1 (fused), if any
        gather_kernel<<<gthBlocks, 256>>>(cur, rowptr, csrsrc, zb, n, l > 0 ? 1 : 0);
        int do_stats = (l < 2);
        if (do_stats) cudaMemsetAsync(stats, 0, 2 * D * sizeof(float));
        mlp_kernel<<<mlpBlocks, 128>>>(zb,
                                       W1 + l * D * D, b1 + l * D,
                                       W2 + l * D * D, b2 + l * D,
                                       nxt, stats, do_stats, n);
        if (do_stats)
            bn_scale_kernel<<<1, D>>>(stats, bng + l * D, bnb + l * D, 1.f / (float)n);
        cur = nxt;
        nxt = (l == 0) ? hB : hA;
    }

    // ---- pooling + head ----
    cudaMemsetAsync(psum, 0, (size_t)G * D * sizeof(float));
    cudaMemsetAsync(pmax, 0, (size_t)G * D * sizeof(int));
    cudaMemsetAsync(pcnt, 0, (size_t)G * sizeof(int));
    int total = n * D;
    pool_kernel<<<(total + 255) / 256, 256>>>(cur, batch, total);

    cudaMemsetAsync(d_out, 0, sizeof(float));
    final_kernel<<<G, 128>>>((const float*)psum, (const int*)pmax, (const int*)pcnt,
                             Wg, bg, pb, pm, y, (float*)d_out);
}

// round 5
// speedup vs baseline: 2.1526x; 1.6533x over previous
#include <cuda_runtime.h>
#include <stdint.h>
#include <math.h>

#define D 128
#define MAXN 100000
#define MAXE 1600000
#define MAXG 512

#define SZS 132           // smem stride (floats) for A-side tiles (z / t)
#define SWS 136           // smem stride (floats) for B-side tiles (weights)
#define MLP_SMEM ((128*SZS + 128*SWS + 256) * 4)

// ---------------- scratch ----------------
__device__ float g_hA[MAXN * D];
__device__ float g_hB[MAXN * D];
__device__ float g_z[MAXN * D];
__device__ int   g_rowptr[MAXN + 1];
__device__ int   g_cursor[MAXN + 1];
__device__ int   g_partial[256];
__device__ int   g_csrsrc[MAXE];
__device__ float g_stats[2 * D];
__device__ float g_bnscale[D];
__device__ float g_bnshift[D];
__device__ float g_psum[MAXG * D];
__device__ int   g_pmax[MAXG * D];
__device__ int   g_pcnt[MAXG];

// ================= CSR build =================
__global__ void hist_kernel(const int* __restrict__ dst, int* __restrict__ deg, int nE)
{
    int e = blockIdx.x * blockDim.x + threadIdx.x;
    if (e < nE) atomicAdd(&deg[dst[e]], 1);
}

#define SCAN_B 1024
__global__ void scan1_kernel(const int* __restrict__ deg, int* __restrict__ rowptr,
                             int* __restrict__ partial, int n)
{
    __shared__ int sh[SCAN_B];
    int i = blockIdx.x * SCAN_B + threadIdx.x;
    int v = (i < n) ? deg[i] : 0;
    sh[threadIdx.x] = v;
    __syncthreads();
    for (int o = 1; o < SCAN_B; o <<= 1) {
        int t = (threadIdx.x >= o) ? sh[threadIdx.x - o] : 0;
        __syncthreads();
        sh[threadIdx.x] += t;
        __syncthreads();
    }
    if (i < n) rowptr[i] = sh[threadIdx.x] - v;
    if (threadIdx.x == SCAN_B - 1) partial[blockIdx.x] = sh[SCAN_B - 1];
}

__global__ void scan2_kernel(int* __restrict__ partial, int nb)
{
    if (threadIdx.x == 0) {
        int acc = 0;
        for (int i = 0; i < nb; i++) { int t = partial[i]; partial[i] = acc; acc += t; }
        partial[nb] = acc;
    }
}

__global__ void scan3_kernel(int* __restrict__ rowptr, const int* __restrict__ partial,
                             int n, int nb)
{
    int i = blockIdx.x * SCAN_B + threadIdx.x;
    if (i < n) rowptr[i] += partial[blockIdx.x];
    if (i == 0) rowptr[n] = partial[nb];
}

__global__ void fill_kernel(const int* __restrict__ src, const int* __restrict__ dst,
                            int* __restrict__ cursor, int* __restrict__ csrsrc, int nE)
{
    int e = blockIdx.x * blockDim.x + threadIdx.x;
    if (e >= nE) return;
    int p = atomicAdd(&cursor[dst[e]], 1);
    csrsrc[p] = src[e];
}

// ================= gather (+ fused BN of previous layer) =================
__global__ void gather_kernel(const float* __restrict__ h,
                              const int* __restrict__ rowptr,
                              const int* __restrict__ csrsrc,
                              float* __restrict__ z, int n, int apply_bn)
{
    int node = (blockIdx.x * blockDim.x + threadIdx.x) >> 5;
    int lane = threadIdx.x & 31;
    if (node >= n) return;
    int beg = rowptr[node], end = rowptr[node + 1];
    const float4* h4 = reinterpret_cast<const float4*>(h);
    float4 acc = h4[(size_t)node * 32 + lane];
    for (int e0 = beg; e0 < end; e0 += 32) {
        int myE = e0 + lane;
        int s = (myE < end) ? csrsrc[myE] : 0;
        int cnt = end - e0; if (cnt > 32) cnt = 32;
        for (int j = 0; j < cnt; j++) {
            int sj = __shfl_sync(0xffffffffu, s, j);
            float4 v = h4[(size_t)sj * 32 + lane];
            acc.x += v.x; acc.y += v.y; acc.z += v.z; acc.w += v.w;
        }
    }
    if (apply_bn) {
        float m = (float)(1 + end - beg);
        int j = lane * 4;
        acc.x = fmaf(acc.x, g_bnscale[j + 0], m * g_bnshift[j + 0]);
        acc.y = fmaf(acc.y, g_bnscale[j + 1], m * g_bnshift[j + 1]);
        acc.z = fmaf(acc.z, g_bnscale[j + 2], m * g_bnshift[j + 2]);
        acc.w = fmaf(acc.w, g_bnscale[j + 3], m * g_bnshift[j + 3]);
    }
    reinterpret_cast<float4*>(z)[(size_t)node * 32 + lane] = acc;
}

// ================= tf32 tensor-core fused MLP =================
__device__ __forceinline__ float f2tf32(float x)
{
    unsigned int u;
    asm("cvt.rna.tf32.f32 %0, %1;" : "=r"(u) : "f"(x));
    return __uint_as_float(u);
}

__device__ __forceinline__ void mma_tf32(float* c, unsigned int a0, unsigned int a1,
                                         unsigned int a2, unsigned int a3,
                                         unsigned int b0, unsigned int b1)
{
    asm volatile("mma.sync.aligned.m16n8k8.row.col.f32.tf32.tf32.f32 "
                 "{%0,%1,%2,%3}, {%4,%5,%6,%7}, {%8,%9}, {%0,%1,%2,%3};"
                 : "+f"(c[0]), "+f"(c[1]), "+f"(c[2]), "+f"(c[3])
                 : "r"(a0), "r"(a1), "r"(a2), "r"(a3), "r"(b0), "r"(b1));
}

__global__ __launch_bounds__(256) void mlp_tc_kernel(
    const float* __restrict__ z,
    const float* __restrict__ W1, const float* __restrict__ b1,
    const float* __restrict__ W2, const float* __restrict__ b2,
    float* __restrict__ hout, int n)
{
    extern __shared__ float sm[];
    float* s_z  = sm;                       // [128][SZS]
    float* s_w  = sm + 128 * SZS;           // [128][SWS]
    float* s_b1 = sm + 128 * SZS + 128 * SWS;
    float* s_b2 = s_b1 + 128;

    int tid  = threadIdx.x;
    int w    = tid >> 5;
    int lane = tid & 31;
    int g    = lane >> 2;       // 0..7
    int q    = lane & 3;        // 0..3
    int base = blockIdx.x * 128;
    int cnt  = n - base; if (cnt > 128) cnt = 128;

    // load biases
    if (tid < 128)              s_b1[tid] = b1[tid];
    else                        s_b2[tid - 128] = b2[tid - 128];

    // load Z tile (tf32-converted, zero pad OOB rows)
    const float4* z4 = reinterpret_cast<const float4*>(z);
    for (int i = tid; i < 128 * 32; i += 256) {
        int r = i >> 5, c4 = i & 31;
        float4 v = (r < cnt) ? z4[(size_t)(base + r) * 32 + c4]
                             : make_float4(0.f, 0.f, 0.f, 0.f);
        v.x = f2tf32(v.x); v.y = f2tf32(v.y); v.z = f2tf32(v.z); v.w = f2tf32(v.w);
        reinterpret_cast<float4*>(s_z + r * SZS)[c4] = v;
    }
    // load W1 tile
    const float4* w4 = reinterpret_cast<const float4*>(W1);
    for (int i = tid; i < 128 * 32; i += 256) {
        int r = i >> 5, c4 = i & 31;
        float4 v = w4[(size_t)r * 32 + c4];
        v.x = f2tf32(v.x); v.y = f2tf32(v.y); v.z = f2tf32(v.z); v.w = f2tf32(v.w);
        reinterpret_cast<float4*>(s_w + r * SWS)[c4] = v;
    }
    __syncthreads();

    int row0 = w * 16 + g;

    // ---- GEMM1: T = relu(Z @ W1 + b1) ----
    float acc[16][4];
#pragma unroll
    for (int nt = 0; nt < 16; nt++) {
        float bv0 = s_b1[nt * 8 + 2 * q], bv1 = s_b1[nt * 8 + 2 * q + 1];
        acc[nt][0] = bv0; acc[nt][1] = bv1; acc[nt][2] = bv0; acc[nt][3] = bv1;
    }
#pragma unroll
    for (int k8 = 0; k8 < 16; k8++) {
        int kc = k8 * 8 + q;
        unsigned int a0 = __float_as_uint(s_z[row0 * SZS + kc]);
        unsigned int a1 = __float_as_uint(s_z[(row0 + 8) * SZS + kc]);
        unsigned int a2 = __float_as_uint(s_z[row0 * SZS + kc + 4]);
        unsigned int a3 = __float_as_uint(s_z[(row0 + 8) * SZS + kc + 4]);
#pragma unroll
        for (int nt = 0; nt < 16; nt++) {
            unsigned int b0 = __float_as_uint(s_w[kc * SWS + nt * 8 + g]);
            unsigned int br = __float_as_uint(s_w[(kc + 4) * SWS + nt * 8 + g]);
            mma_tf32(acc[nt], a0, a1, a2, a3, b0, br);
        }
    }
    __syncthreads();   // all reads of s_z / s_w done

    // store relu(T) as tf32 into the freed s_z; load W2 into s_w
#pragma unroll
    for (int nt = 0; nt < 16; nt++) {
        int col = nt * 8 + 2 * q;
        float2 v0 = make_float2(f2tf32(fmaxf(acc[nt][0], 0.f)), f2tf32(fmaxf(acc[nt][1], 0.f)));
        float2 v1 = make_float2(f2tf32(fmaxf(acc[nt][2], 0.f)), f2tf32(fmaxf(acc[nt][3], 0.f)));
        *reinterpret_cast<float2*>(s_z + row0 * SZS + col)       = v0;
        *reinterpret_cast<float2*>(s_z + (row0 + 8) * SZS + col) = v1;
    }
    const float4* w24 = reinterpret_cast<const float4*>(W2);
    for (int i = tid; i < 128 * 32; i += 256) {
        int r = i >> 5, c4 = i & 31;
        float4 v = w24[(size_t)r * 32 + c4];
        v.x = f2tf32(v.x); v.y = f2tf32(v.y); v.z = f2tf32(v.z); v.w = f2tf32(v.w);
        reinterpret_cast<float4*>(s_w + r * SWS)[c4] = v;
    }
    __syncthreads();

    // ---- GEMM2: H = relu(T @ W2 + b2) ----
#pragma unroll
    for (int nt = 0; nt < 16; nt++) {
        float bv0 = s_b2[nt * 8 + 2 * q], bv1 = s_b2[nt * 8 + 2 * q + 1];
        acc[nt][0] = bv0; acc[nt][1] = bv1; acc[nt][2] = bv0; acc[nt][3] = bv1;
    }
#pragma unroll
    for (int k8 = 0; k8 < 16; k8++) {
        int kc = k8 * 8 + q;
        unsigned int a0 = __float_as_uint(s_z[row0 * SZS + kc]);
        unsigned int a1 = __float_as_uint(s_z[(row0 + 8) * SZS + kc]);
        unsigned int a2 = __float_as_uint(s_z[row0 * SZS + kc + 4]);
        unsigned int a3 = __float_as_uint(s_z[(row0 + 8) * SZS + kc + 4]);
#pragma unroll
        for (int nt = 0; nt < 16; nt++) {
            unsigned int b0 = __float_as_uint(s_w[kc * SWS + nt * 8 + g]);
            unsigned int br = __float_as_uint(s_w[(kc + 4) * SWS + nt * 8 + g]);
            mma_tf32(acc[nt], a0, a1, a2, a3, b0, br);
        }
    }

    // epilogue: relu + store
    bool ok0 = (row0 < cnt), ok1 = (row0 + 8 < cnt);
    float* o0 = hout + (size_t)(base + row0) * 128;
    float* o1 = hout + (size_t)(base + row0 + 8) * 128;
#pragma unroll
    for (int nt = 0; nt < 16; nt++) {
        int col = nt * 8 + 2 * q;
        if (ok0) *reinterpret_cast<float2*>(o0 + col) =
            make_float2(fmaxf(acc[nt][0], 0.f), fmaxf(acc[nt][1], 0.f));
        if (ok1) *reinterpret_cast<float2*>(o1 + col) =
            make_float2(fmaxf(acc[nt][2], 0.f), fmaxf(acc[nt][3], 0.f));
    }
}

// ================= per-feature stats over hout =================
__global__ void stats_kernel(const float* __restrict__ h, float* __restrict__ stats, int n4)
{
    __shared__ float s_sum[D], s_sq[D];
    if (threadIdx.x < D) { s_sum[threadIdx.x] = 0.f; s_sq[threadIdx.x] = 0.f; }
    __syncthreads();
    int i0 = blockIdx.x * blockDim.x + threadIdx.x;
    int stride = gridDim.x * blockDim.x;       // multiple of 32
    float ls0 = 0, ls1 = 0, ls2 = 0, ls3 = 0, lq0 = 0, lq1 = 0, lq2 = 0, lq3 = 0;
    for (int i = i0; i < n4; i += stride) {
        float4 v = reinterpret_cast<const float4*>(h)[i];
        ls0 += v.x; lq0 += v.x * v.x;
        ls1 += v.y; lq1 += v.y * v.y;
        ls2 += v.z; lq2 += v.z * v.z;
        ls3 += v.w; lq3 += v.w * v.w;
    }
    int c = (i0 & 31) * 4;
    atomicAdd(&s_sum[c + 0], ls0); atomicAdd(&s_sq[c + 0], lq0);
    atomicAdd(&s_sum[c + 1], ls1); atomicAdd(&s_sq[c + 1], lq1);
    atomicAdd(&s_sum[c + 2], ls2); atomicAdd(&s_sq[c + 2], lq2);
    atomicAdd(&s_sum[c + 3], ls3); atomicAdd(&s_sq[c + 3], lq3);
    __syncthreads();
    if (threadIdx.x < D) {
        atomicAdd(&stats[threadIdx.x], s_sum[threadIdx.x]);
        atomicAdd(&stats[D + threadIdx.x], s_sq[threadIdx.x]);
    }
}

__global__ void bn_scale_kernel(const float* __restrict__ stats,
                                const float* __restrict__ gamma,
                                const float* __restrict__ beta, float inv_n)
{
    int j = threadIdx.x;
    float mu = stats[j] * inv_n;
    float var = stats[D + j] * inv_n - mu * mu;
    float sc = gamma[j] * rsqrtf(var + 1e-5f);
    g_bnscale[j] = sc;
    g_bnshift[j] = beta[j] - mu * sc;
}

// ================= pooling =================
__global__ void pool_kernel(const float* __restrict__ h,
                            const int* __restrict__ batch, int total)
{
    int gid = blockIdx.x * blockDim.x + threadIdx.x;
    if (gid >= total) return;
    int node = gid >> 7;
    int j = gid & 127;
    int b = batch[node];
    float v = h[gid];
    atomicAdd(&g_psum[b * D + j], v);
    atomicMax(&g_pmax[b * D + j], __float_as_int(v));
    if (j == 0) atomicAdd(&g_pcnt[b], 1);
}

// ================= final head =================
__device__ __forceinline__ float breduce128(float v, float* s4)
{
    int lane = threadIdx.x & 31, w = threadIdx.x >> 5;
#pragma unroll
    for (int o = 16; o; o >>= 1) v += __shfl_down_sync(0xffffffffu, v, o);
    if (lane == 0) s4[w] = v;
    __syncthreads();
    float r = s4[0] + s4[1] + s4[2] + s4[3];
    __syncthreads();
    return r;
}

__global__ __launch_bounds__(128) void final_kernel(
    const float* __restrict__ psum, const int* __restrict__ pmax,
    const int* __restrict__ pcnt,
    const float* __restrict__ Wg, const float* __restrict__ bg,
    const float* __restrict__ pb, const float* __restrict__ pm,
    const int* __restrict__ y, float* __restrict__ out)
{
    __shared__ float s_gx[2 * D];
    __shared__ float s4[4];
    int g = blockIdx.x, j = threadIdx.x;

    float cntf = fmaxf((float)pcnt[g], 1.f);
    s_gx[j]     = psum[g * D + j] / cntf;
    s_gx[D + j] = __int_as_float(pmax[g * D + j]);
    __syncthreads();

    float rep = bg[j];
#pragma unroll
    for (int k = 0; k < 2 * D; k++) rep = fmaf(s_gx[k], Wg[k * D + j], rep);

    float nrm = breduce128(rep * rep, s4);
    float feat = rep / fmaxf(sqrtf(nrm), 1e-12f);

    float pbj = pb[j], pmj = pm[j];
    float nb = breduce128(pbj * pbj, s4);
    float nm = breduce128(pmj * pmj, s4);
    pbj /= fmaxf(sqrtf(nb), 1e-12f);
    pmj /= fmaxf(sqrtf(nm), 1e-12f);

    float cb = breduce128(feat * pbj, s4);
    float cm = breduce128(feat * pmj, s4);

    if (j == 0) {
        bool mal = (y[g] == 1);
        float a = mal ? cb * cb : (1.f - cb) * (1.f - cb);
        float b = mal ? (1.f - cm) * (1.f - cm) : cm * cm;
        atomicAdd(out, a + b);
    }
}

// ================= host =================
extern "C" void kernel_launch(void* const* d_in, const int* in_sizes, int n_in,
                              void* d_out, int out_size)
{
    const float* x   = (const float*)d_in[0];
    const int* ei    = (const int*)d_in[1];
    const int* batch = (const int*)d_in[2];
    const int* y     = (const int*)d_in[3];
    const float* W1  = (const float*)d_in[4];
    const float* b1  = (const float*)d_in[5];
    const float* W2  = (const float*)d_in[6];
    const float* b2  = (const float*)d_in[7];
    const float* bng = (const float*)d_in[8];
    const float* bnb = (const float*)d_in[9];
    const float* Wg  = (const float*)d_in[10];
    const float* bg  = (const float*)d_in[11];
    const float* pb  = (const float*)d_in[12];
    const float* pm  = (const float*)d_in[13];

    int n  = in_sizes[0] / D;
    int nE = in_sizes[1] / 2;
    int G  = in_sizes[3];
    const int* src = ei;
    const int* dst = ei + nE;

    float *hA, *hB, *zb, *stats;
    int *rowptr, *cursor, *partial, *csrsrc;
    void *psum, *pmax, *pcnt;
    cudaGetSymbolAddress((void**)&hA, g_hA);
    cudaGetSymbolAddress((void**)&hB, g_hB);
    cudaGetSymbolAddress((void**)&zb, g_z);
    cudaGetSymbolAddress((void**)&stats, g_stats);
    cudaGetSymbolAddress((void**)&rowptr, g_rowptr);
    cudaGetSymbolAddress((void**)&cursor, g_cursor);
    cudaGetSymbolAddress((void**)&partial, g_partial);
    cudaGetSymbolAddress((void**)&csrsrc, g_csrsrc);
    cudaGetSymbolAddress(&psum, g_psum);
    cudaGetSymbolAddress(&pmax, g_pmax);
    cudaGetSymbolAddress(&pcnt, g_pcnt);

    cudaFuncSetAttribute(mlp_tc_kernel, cudaFuncAttributeMaxDynamicSharedMemorySize, MLP_SMEM);

    // ---- CSR build (once) ----
    int nb = (n + SCAN_B - 1) / SCAN_B;
    cudaMemsetAsync(cursor, 0, (n + 1) * sizeof(int));
    hist_kernel<<<(nE + 255) / 256, 256>>>(dst, cursor, nE);
    scan1_kernel<<<nb, SCAN_B>>>(cursor, rowptr, partial, n);
    scan2_kernel<<<1, 32>>>(partial, nb);
    scan3_kernel<<<nb, SCAN_B>>>(rowptr, partial, n, nb);
    cudaMemcpyAsync(cursor, rowptr, n * sizeof(int), cudaMemcpyDeviceToDevice);
    fill_kernel<<<(nE + 255) / 256, 256>>>(src, dst, cursor, csrsrc, nE);

    // ---- layers ----
    const float* cur = x;
    float* nxt = hA;
    int mlpBlocks = (n + 127) / 128;
    int gthBlocks = (n * 32 + 255) / 256;

    for (int l = 0; l < 3; l++) {
        gather_kernel<<<gthBlocks, 256>>>(cur, rowptr, csrsrc, zb, n, l > 0 ? 1 : 0);
        mlp_tc_kernel<<<mlpBlocks, 256, MLP_SMEM>>>(zb,
                                                    W1 + l * D * D, b1 + l * D,
                                                    W2 + l * D * D, b2 + l * D,
                                                    nxt, n);
        if (l < 2) {
            cudaMemsetAsync(stats, 0, 2 * D * sizeof(float));
            stats_kernel<<<296, 256>>>(nxt, stats, n * 32);
            bn_scale_kernel<<<1, D>>>(stats, bng + l * D, bnb + l * D, 1.f / (float)n);
        }
        cur = nxt;
        nxt = (l == 0) ? hB : hA;
    }

    // ---- pooling + head ----
    cudaMemsetAsync(psum, 0, (size_t)G * D * sizeof(float));
    cudaMemsetAsync(pmax, 0, (size_t)G * D * sizeof(int));
    cudaMemsetAsync(pcnt, 0, (size_t)G * sizeof(int));
    int total = n * D;
    pool_kernel<<<(total + 255) / 256, 256>>>(cur, batch, total);

    cudaMemsetAsync(d_out, 0, sizeof(float));
    final_kernel<<<G, 128>>>((const float*)psum, (const int*)pmax, (const int*)pcnt,
                             Wg, bg, pb, pm, y, (float*)d_out);
}

// round 6
// speedup vs baseline: 2.3044x; 1.0705x over previous
#include <cuda_runtime.h>
#include <cuda_fp16.h>
#include <stdint.h>
#include <math.h>

#define D 128
#define MAXN 100000
#define MAXE 1600000
#define MAXG 512

#define SZS 132           // smem stride (floats) for A-side tiles (z / t)
#define SWS 136           // smem stride (floats) for B-side tiles (weights)
#define MLP_SMEM ((128*SZS + 128*SWS + 256 + 256) * 4)

// ---------------- scratch ----------------
__device__ __half g_h16A[MAXN * D];
__device__ __half g_h16B[MAXN * D];
__device__ __half g_x16[MAXN * D];
__device__ __half g_z16[MAXN * D];
__device__ int   g_rowptr[MAXN + 1];
__device__ int   g_cursor[MAXN + 1];
__device__ int   g_partial[256];
__device__ int   g_csrsrc[MAXE];
__device__ float g_stats[2 * D];
__device__ float g_bnscale[D];
__device__ float g_bnshift[D];
__device__ float g_psum[MAXG * D];
__device__ int   g_pmax[MAXG * D];
__device__ int   g_pcnt[MAXG];

// ================= CSR build =================
__global__ void hist_kernel(const int* __restrict__ dst, int* __restrict__ deg, int nE)
{
    int e = blockIdx.x * blockDim.x + threadIdx.x;
    if (e < nE) atomicAdd(&deg[dst[e]], 1);
}

#define SCAN_B 1024
__global__ void scan1_kernel(const int* __restrict__ deg, int* __restrict__ rowptr,
                             int* __restrict__ partial, int n)
{
    __shared__ int sh[SCAN_B];
    int i = blockIdx.x * SCAN_B + threadIdx.x;
    int v = (i < n) ? deg[i] : 0;
    sh[threadIdx.x] = v;
    __syncthreads();
    for (int o = 1; o < SCAN_B; o <<= 1) {
        int t = (threadIdx.x >= o) ? sh[threadIdx.x - o] : 0;
        __syncthreads();
        sh[threadIdx.x] += t;
        __syncthreads();
    }
    if (i < n) rowptr[i] = sh[threadIdx.x] - v;
    if (threadIdx.x == SCAN_B - 1) partial[blockIdx.x] = sh[SCAN_B - 1];
}

__global__ void scan2_kernel(int* __restrict__ partial, int nb)
{
    if (threadIdx.x == 0) {
        int acc = 0;
        for (int i = 0; i < nb; i++) { int t = partial[i]; partial[i] = acc; acc += t; }
        partial[nb] = acc;
    }
}

__global__ void scan3_kernel(int* __restrict__ rowptr, const int* __restrict__ partial,
                             int n, int nb)
{
    int i = blockIdx.x * SCAN_B + threadIdx.x;
    if (i < n) rowptr[i] += partial[blockIdx.x];
    if (i == 0) rowptr[n] = partial[nb];
}

__global__ void fill_kernel(const int* __restrict__ src, const int* __restrict__ dst,
                            int* __restrict__ cursor, int* __restrict__ csrsrc, int nE)
{
    int e = blockIdx.x * blockDim.x + threadIdx.x;
    if (e >= nE) return;
    int p = atomicAdd(&cursor[dst[e]], 1);
    csrsrc[p] = src[e];
}

// node count per graph
__global__ void cnt_kernel(const int* __restrict__ batch, int* __restrict__ pcnt, int n)
{
    int i = blockIdx.x * blockDim.x + threadIdx.x;
    if (i < n) atomicAdd(&pcnt[batch[i]], 1);
}

// fp32 -> fp16 conversion (x once)
__global__ void x2h_kernel(const float* __restrict__ x, __half* __restrict__ o, int n2)
{
    int i = blockIdx.x * blockDim.x + threadIdx.x;
    if (i >= n2) return;
    float2 f = reinterpret_cast<const float2*>(x)[i];
    reinterpret_cast<__half2*>(o)[i] = __floats2half2_rn(f.x, f.y);
}

// ================= gather (fp16 in/out, fp32 accumulate, fused BN) ===============
__global__ void gather16_kernel(const __half* __restrict__ h,
                                const int* __restrict__ rowptr,
                                const int* __restrict__ csrsrc,
                                __half* __restrict__ z, int n, int apply_bn)
{
    int node = (blockIdx.x * blockDim.x + threadIdx.x) >> 5;
    int lane = threadIdx.x & 31;
    if (node >= n) return;
    int beg = rowptr[node], end = rowptr[node + 1];
    const uint2* h2 = reinterpret_cast<const uint2*>(h);   // 32 uint2 (= 4 halves) per row
    uint2 u = h2[(size_t)node * 32 + lane];
    float2 f0 = __half22float2(*reinterpret_cast<__half2*>(&u.x));
    float2 f1 = __half22float2(*reinterpret_cast<__half2*>(&u.y));
    float4 acc = make_float4(f0.x, f0.y, f1.x, f1.y);
    for (int e0 = beg; e0 < end; e0 += 32) {
        int myE = e0 + lane;
        int s = (myE < end) ? csrsrc[myE] : 0;
        int cnt = end - e0; if (cnt > 32) cnt = 32;
        for (int j = 0; j < cnt; j++) {
            int sj = __shfl_sync(0xffffffffu, s, j);
            uint2 v = h2[(size_t)sj * 32 + lane];
            float2 g0 = __half22float2(*reinterpret_cast<__half2*>(&v.x));
            float2 g1 = __half22float2(*reinterpret_cast<__half2*>(&v.y));
            acc.x += g0.x; acc.y += g0.y; acc.z += g1.x; acc.w += g1.y;
        }
    }
    if (apply_bn) {
        float m = (float)(1 + end - beg);
        int j = lane * 4;
        acc.x = fmaf(acc.x, g_bnscale[j + 0], m * g_bnshift[j + 0]);
        acc.y = fmaf(acc.y, g_bnscale[j + 1], m * g_bnshift[j + 1]);
        acc.z = fmaf(acc.z, g_bnscale[j + 2], m * g_bnshift[j + 2]);
        acc.w = fmaf(acc.w, g_bnscale[j + 3], m * g_bnshift[j + 3]);
    }
    __half2 o0 = __floats2half2_rn(acc.x, acc.y);
    __half2 o1 = __floats2half2_rn(acc.z, acc.w);
    uint2 out;
    out.x = *reinterpret_cast<unsigned int*>(&o0);
    out.y = *reinterpret_cast<unsigned int*>(&o1);
    reinterpret_cast<uint2*>(z)[(size_t)node * 32 + lane] = out;
}

// ================= tf32 tensor-core fused MLP =================
__device__ __forceinline__ float f2tf32(float x)
{
    unsigned int u;
    asm("cvt.rna.tf32.f32 %0, %1;" : "=r"(u) : "f"(x));
    return __uint_as_float(u);
}

__device__ __forceinline__ void mma_tf32(float* c, unsigned int a0, unsigned int a1,
                                         unsigned int a2, unsigned int a3,
                                         unsigned int b0, unsigned int b1)
{
    asm volatile("mma.sync.aligned.m16n8k8.row.col.f32.tf32.tf32.f32 "
                 "{%0,%1,%2,%3}, {%4,%5,%6,%7}, {%8,%9}, {%0,%1,%2,%3};"
                 : "+f"(c[0]), "+f"(c[1]), "+f"(c[2]), "+f"(c[3])
                 : "r"(a0), "r"(a1), "r"(a2), "r"(a3), "r"(b0), "r"(b1));
}

// mode 0: write h16 out + BN stats.  mode 2: fused mean/max pooling, no h out.
__global__ __launch_bounds__(256) void mlp_tc_kernel(
    const __half* __restrict__ z,
    const float* __restrict__ W1, const float* __restrict__ b1,
    const float* __restrict__ W2, const float* __restrict__ b2,
    __half* __restrict__ hout, float* __restrict__ stats,
    const int* __restrict__ batch, float* __restrict__ psum, int* __restrict__ pmax,
    int n, int mode)
{
    extern __shared__ float sm[];
    float* s_z  = sm;                       // [128][SZS]
    float* s_w  = sm + 128 * SZS;           // [128][SWS]
    float* s_b1 = sm + 128 * SZS + 128 * SWS;
    float* s_b2 = s_b1 + 128;
    float* s_st = s_b2 + 128;               // [256] sum / sumsq

    int tid  = threadIdx.x;
    int w    = tid >> 5;
    int lane = tid & 31;
    int g    = lane >> 2;       // 0..7
    int q    = lane & 3;        // 0..3
    int base = blockIdx.x * 128;
    int cnt  = n - base; if (cnt > 128) cnt = 128;

    if (tid < 128)      s_b1[tid] = b1[tid];
    else                s_b2[tid - 128] = b2[tid - 128];
    if (tid < 256)      s_st[tid] = 0.f;     // always cheap

    // load Z tile (fp16 -> fp32; values already have <=10 mantissa bits -> valid tf32)
    const uint2* z2 = reinterpret_cast<const uint2*>(z);
    for (int i = tid; i < 128 * 32; i += 256) {
        int r = i >> 5, c = i & 31;
        uint2 u = (r < cnt) ? z2[(size_t)(base + r) * 32 + c] : make_uint2(0u, 0u);
        float2 f0 = __half22float2(*reinterpret_cast<__half2*>(&u.x));
        float2 f1 = __half22float2(*reinterpret_cast<__half2*>(&u.y));
        *reinterpret_cast<float4*>(s_z + r * SZS + c * 4) = make_float4(f0.x, f0.y, f1.x, f1.y);
    }
    // load W1
    const float4* w4 = reinterpret_cast<const float4*>(W1);
    for (int i = tid; i < 128 * 32; i += 256) {
        int r = i >> 5, c4 = i & 31;
        float4 v = w4[(size_t)r * 32 + c4];
        v.x = f2tf32(v.x); v.y = f2tf32(v.y); v.z = f2tf32(v.z); v.w = f2tf32(v.w);
        reinterpret_cast<float4*>(s_w + r * SWS)[c4] = v;
    }
    __syncthreads();

    int row0 = w * 16 + g;

    // ---- GEMM1: T = relu(Z @ W1 + b1) ----
    float acc[16][4];
#pragma unroll
    for (int nt = 0; nt < 16; nt++) {
        float bv0 = s_b1[nt * 8 + 2 * q], bv1 = s_b1[nt * 8 + 2 * q + 1];
        acc[nt][0] = bv0; acc[nt][1] = bv1; acc[nt][2] = bv0; acc[nt][3] = bv1;
    }
#pragma unroll
    for (int k8 = 0; k8 < 16; k8++) {
        int kc = k8 * 8 + q;
        unsigned int a0 = __float_as_uint(s_z[row0 * SZS + kc]);
        unsigned int a1 = __float_as_uint(s_z[(row0 + 8) * SZS + kc]);
        unsigned int a2 = __float_as_uint(s_z[row0 * SZS + kc + 4]);
        unsigned int a3 = __float_as_uint(s_z[(row0 + 8) * SZS + kc + 4]);
#pragma unroll
        for (int nt = 0; nt < 16; nt++) {
            unsigned int b0 = __float_as_uint(s_w[kc * SWS + nt * 8 + g]);
            unsigned int br = __float_as_uint(s_w[(kc + 4) * SWS + nt * 8 + g]);
            mma_tf32(acc[nt], a0, a1, a2, a3, b0, br);
        }
    }
    __syncthreads();

    // store relu(T) as tf32 into freed s_z; load W2
#pragma unroll
    for (int nt = 0; nt < 16; nt++) {
        int col = nt * 8 + 2 * q;
        float2 v0 = make_float2(f2tf32(fmaxf(acc[nt][0], 0.f)), f2tf32(fmaxf(acc[nt][1], 0.f)));
        float2 v1 = make_float2(f2tf32(fmaxf(acc[nt][2], 0.f)), f2tf32(fmaxf(acc[nt][3], 0.f)));
        *reinterpret_cast<float2*>(s_z + row0 * SZS + col)       = v0;
        *reinterpret_cast<float2*>(s_z + (row0 + 8) * SZS + col) = v1;
    }
    const float4* w24 = reinterpret_cast<const float4*>(W2);
    for (int i = tid; i < 128 * 32; i += 256) {
        int r = i >> 5, c4 = i & 31;
        float4 v = w24[(size_t)r * 32 + c4];
        v.x = f2tf32(v.x); v.y = f2tf32(v.y); v.z = f2tf32(v.z); v.w = f2tf32(v.w);
        reinterpret_cast<float4*>(s_w + r * SWS)[c4] = v;
    }
    __syncthreads();

    // ---- GEMM2: H = relu(T @ W2 + b2) ----
#pragma unroll
    for (int nt = 0; nt < 16; nt++) {
        float bv0 = s_b2[nt * 8 + 2 * q], bv1 = s_b2[nt * 8 + 2 * q + 1];
        acc[nt][0] = bv0; acc[nt][1] = bv1; acc[nt][2] = bv0; acc[nt][3] = bv1;
    }
#pragma unroll
    for (int k8 = 0; k8 < 16; k8++) {
        int kc = k8 * 8 + q;
        unsigned int a0 = __float_as_uint(s_z[row0 * SZS + kc]);
        unsigned int a1 = __float_as_uint(s_z[(row0 + 8) * SZS + kc]);
        unsigned int a2 = __float_as_uint(s_z[row0 * SZS + kc + 4]);
        unsigned int a3 = __float_as_uint(s_z[(row0 + 8) * SZS + kc + 4]);
#pragma unroll
        for (int nt = 0; nt < 16; nt++) {
            unsigned int b0 = __float_as_uint(s_w[kc * SWS + nt * 8 + g]);
            unsigned int br = __float_as_uint(s_w[(kc + 4) * SWS + nt * 8 + g]);
            mma_tf32(acc[nt], a0, a1, a2, a3, b0, br);
        }
    }

    bool ok0 = (row0 < cnt), ok1 = (row0 + 8 < cnt);

    if (mode != 2) {
        // ---- epilogue: relu, write fp16, accumulate BN stats ----
        __half2* o0 = reinterpret_cast<__half2*>(hout + (size_t)(base + row0) * 128);
        __half2* o1 = reinterpret_cast<__half2*>(hout + (size_t)(base + row0 + 8) * 128);
#pragma unroll
        for (int nt = 0; nt < 16; nt++) {
            int c0 = nt * 8 + 2 * q;
            float v00 = fmaxf(acc[nt][0], 0.f), v01 = fmaxf(acc[nt][1], 0.f);
            float v10 = fmaxf(acc[nt][2], 0.f), v11 = fmaxf(acc[nt][3], 0.f);
            if (ok0) o0[nt * 4 + q] = __floats2half2_rn(v00, v01);
            if (ok1) o1[nt * 4 + q] = __floats2half2_rn(v10, v11);
            float a00 = ok0 ? v00 : 0.f, a01 = ok0 ? v01 : 0.f;
            float a10 = ok1 ? v10 : 0.f, a11 = ok1 ? v11 : 0.f;
            float s0 = a00 + a10, s1 = a01 + a11;
            float q0 = a00 * a00 + a10 * a10, q1 = a01 * a01 + a11 * a11;
#pragma unroll
            for (int m = 4; m <= 16; m <<= 1) {       // reduce over the 8 g-lanes
                s0 += __shfl_xor_sync(0xffffffffu, s0, m);
                s1 += __shfl_xor_sync(0xffffffffu, s1, m);
                q0 += __shfl_xor_sync(0xffffffffu, q0, m);
                q1 += __shfl_xor_sync(0xffffffffu, q1, m);
            }
            if (g == 0) {
                atomicAdd(&s_st[c0],       s0);
                atomicAdd(&s_st[c0 + 1],   s1);
                atomicAdd(&s_st[128 + c0], q0);
                atomicAdd(&s_st[128 + c0 + 1], q1);
            }
        }
        __syncthreads();
        if (tid < 256) atomicAdd(&stats[tid], s_st[tid]);
    } else {
        // ---- epilogue: fused mean/max pooling ----
        int b0 = ok0 ? batch[base + row0] : 0;
        int b1i = ok1 ? batch[base + row0 + 8] : 0;
#pragma unroll
        for (int nt = 0; nt < 16; nt++) {
            int c0 = nt * 8 + 2 * q;
            float v00 = fmaxf(acc[nt][0], 0.f), v01 = fmaxf(acc[nt][1], 0.f);
            float v10 = fmaxf(acc[nt][2], 0.f), v11 = fmaxf(acc[nt][3], 0.f);
            if (ok0) {
                atomicAdd(&psum[b0 * D + c0],     v00);
                atomicAdd(&psum[b0 * D + c0 + 1], v01);
                atomicMax(&pmax[b0 * D + c0],     __float_as_int(v00));
                atomicMax(&pmax[b0 * D + c0 + 1], __float_as_int(v01));
            }
            if (ok1) {
                atomicAdd(&psum[b1i * D + c0],     v10);
                atomicAdd(&psum[b1i * D + c0 + 1], v11);
                atomicMax(&pmax[b1i * D + c0],     __float_as_int(v10));
                atomicMax(&pmax[b1i * D + c0 + 1], __float_as_int(v11));
            }
        }
    }
}

__global__ void bn_scale_kernel(const float* __restrict__ stats,
                                const float* __restrict__ gamma,
                                const float* __restrict__ beta, float inv_n)
{
    int j = threadIdx.x;
    float mu = stats[j] * inv_n;
    float var = stats[D + j] * inv_n - mu * mu;
    float sc = gamma[j] * rsqrtf(var + 1e-5f);
    g_bnscale[j] = sc;
    g_bnshift[j] = beta[j] - mu * sc;
}

// ================= final head =================
__device__ __forceinline__ float breduce128(float v, float* s4)
{
    int lane = threadIdx.x & 31, w = threadIdx.x >> 5;
#pragma unroll
    for (int o = 16; o; o >>= 1) v += __shfl_down_sync(0xffffffffu, v, o);
    if (lane == 0) s4[w] = v;
    __syncthreads();
    float r = s4[0] + s4[1] + s4[2] + s4[3];
    __syncthreads();
    return r;
}

__global__ __launch_bounds__(128) void final_kernel(
    const float* __restrict__ psum, const int* __restrict__ pmax,
    const int* __restrict__ pcnt,
    const float* __restrict__ Wg, const float* __restrict__ bg,
    const float* __restrict__ pb, const float* __restrict__ pm,
    const int* __restrict__ y, float* __restrict__ out)
{
    __shared__ float s_gx[2 * D];
    __shared__ float s4[4];
    int g = blockIdx.x, j = threadIdx.x;

    float cntf = fmaxf((float)pcnt[g], 1.f);
    s_gx[j]     = psum[g * D + j] / cntf;
    s_gx[D + j] = __int_as_float(pmax[g * D + j]);
    __syncthreads();

    float rep = bg[j];
#pragma unroll
    for (int k = 0; k < 2 * D; k++) rep = fmaf(s_gx[k], Wg[k * D + j], rep);

    float nrm = breduce128(rep * rep, s4);
    float feat = rep / fmaxf(sqrtf(nrm), 1e-12f);

    float pbj = pb[j], pmj = pm[j];
    float nb = breduce128(pbj * pbj, s4);
    float nm = breduce128(pmj * pmj, s4);
    pbj /= fmaxf(sqrtf(nb), 1e-12f);
    pmj /= fmaxf(sqrtf(nm), 1e-12f);

    float cb = breduce128(feat * pbj, s4);
    float cm = breduce128(feat * pmj, s4);

    if (j == 0) {
        bool mal = (y[g] == 1);
        float a = mal ? cb * cb : (1.f - cb) * (1.f - cb);
        float b = mal ? (1.f - cm) * (1.f - cm) : cm * cm;
        atomicAdd(out, a + b);
    }
}

// ================= host =================
extern "C" void kernel_launch(void* const* d_in, const int* in_sizes, int n_in,
                              void* d_out, int out_size)
{
    const float* x   = (const float*)d_in[0];
    const int* ei    = (const int*)d_in[1];
    const int* batch = (const int*)d_in[2];
    const int* y     = (const int*)d_in[3];
    const float* W1  = (const float*)d_in[4];
    const float* b1  = (const float*)d_in[5];
    const float* W2  = (const float*)d_in[6];
    const float* b2  = (const float*)d_in[7];
    const float* bng = (const float*)d_in[8];
    const float* bnb = (const float*)d_in[9];
    const float* Wg  = (const float*)d_in[10];
    const float* bg  = (const float*)d_in[11];
    const float* pb  = (const float*)d_in[12];
    const float* pm  = (const float*)d_in[13];

    int n  = in_sizes[0] / D;
    int nE = in_sizes[1] / 2;
    int G  = in_sizes[3];
    const int* src = ei;
    const int* dst = ei + nE;

    __half *h16A, *h16B, *x16, *z16;
    float *stats;
    int *rowptr, *cursor, *partial, *csrsrc;
    void *psum, *pmax, *pcnt;
    cudaGetSymbolAddress((void**)&h16A, g_h16A);
    cudaGetSymbolAddress((void**)&h16B, g_h16B);
    cudaGetSymbolAddress((void**)&x16, g_x16);
    cudaGetSymbolAddress((void**)&z16, g_z16);
    cudaGetSymbolAddress((void**)&stats, g_stats);
    cudaGetSymbolAddress((void**)&rowptr, g_rowptr);
    cudaGetSymbolAddress((void**)&cursor, g_cursor);
    cudaGetSymbolAddress((void**)&partial, g_partial);
    cudaGetSymbolAddress((void**)&csrsrc, g_csrsrc);
    cudaGetSymbolAddress(&psum, g_psum);
    cudaGetSymbolAddress(&pmax, g_pmax);
    cudaGetSymbolAddress(&pcnt, g_pcnt);

    cudaFuncSetAttribute(mlp_tc_kernel, cudaFuncAttributeMaxDynamicSharedMemorySize, MLP_SMEM);

    // ---- CSR build + pooling prep (once) ----
    int nb = (n + SCAN_B - 1) / SCAN_B;
    cudaMemsetAsync(cursor, 0, (n + 1) * sizeof(int));
    hist_kernel<<<(nE + 255) / 256, 256>>>(dst, cursor, nE);
    scan1_kernel<<<nb, SCAN_B>>>(cursor, rowptr, partial, n);
    scan2_kernel<<<1, 32>>>(partial, nb);
    scan3_kernel<<<nb, SCAN_B>>>(rowptr, partial, n, nb);
    cudaMemcpyAsync(cursor, rowptr, n * sizeof(int), cudaMemcpyDeviceToDevice);
    fill_kernel<<<(nE + 255) / 256, 256>>>(src, dst, cursor, csrsrc, nE);

    cudaMemsetAsync(pcnt, 0, (size_t)G * sizeof(int));
    cudaMemsetAsync(psum, 0, (size_t)G * D * sizeof(float));
    cudaMemsetAsync(pmax, 0, (size_t)G * D * sizeof(int));
    cnt_kernel<<<(n + 255) / 256, 256>>>(batch, (int*)pcnt, n);
    x2h_kernel<<<(n * 64 + 255) / 256, 256>>>(x, x16, n * 64);

    // ---- layers ----
    const __half* cur = x16;
    __half* nxt = h16A;
    int mlpBlocks = (n + 127) / 128;
    int gthBlocks = (n * 32 + 255) / 256;

    for (int l = 0; l < 3; l++) {
        gather16_kernel<<<gthBlocks, 256>>>(cur, rowptr, csrsrc, z16, n, l > 0 ? 1 : 0);
        if (l < 2) {
            cudaMemsetAsync(stats, 0, 2 * D * sizeof(float));
            mlp_tc_kernel<<<mlpBlocks, 256, MLP_SMEM>>>(z16,
                W1 + l * D * D, b1 + l * D, W2 + l * D * D, b2 + l * D,
                nxt, stats, batch, (float*)psum, (int*)pmax, n, 0);
            bn_scale_kernel<<<1, D>>>(stats, bng + l * D, bnb + l * D, 1.f / (float)n);
            cur = nxt;
            nxt = (l == 0) ? h16B : h16A;
        } else {
            mlp_tc_kernel<<<mlpBlocks, 256, MLP_SMEM>>>(z16,
                W1 + l * D * D, b1 + l * D, W2 + l * D * D, b2 + l * D,
                nullptr, stats, batch, (float*)psum, (int*)pmax, n, 2);
        }
    }

    cudaMemsetAsync(d_out, 0, sizeof(float));
    final_kernel<<<G, 128>>>((const float*)psum, (const int*)pmax, (const int*)pcnt,
                             Wg, bg, pb, pm, y, (float*)d_out);
}

// round 7
// speedup vs baseline: 2.3345x; 1.0130x over previous
#include <cuda_runtime.h>
#include <cuda_fp16.h>
#include <stdint.h>
#include <math.h>

#define D 128
#define MAXN 100000
#define MAXE 1600000
#define MAXG 512

#define SZS 132           // smem stride (floats) for A-side tiles (z / t)
#define SWS 132           // smem stride (floats) for B-side tiles (weights, [k][g*16+nt])
#define MLP_SMEM ((128*SZS + 128*SWS + 256 + 256) * 4)

// ---------------- scratch ----------------
__device__ __half g_h16A[MAXN * D];
__device__ __half g_h16B[MAXN * D];
__device__ __half g_x16[MAXN * D];
__device__ __half g_z16[MAXN * D];
__device__ int   g_rowptr[MAXN + 1];
__device__ int   g_cursor[MAXN + 1];
__device__ int   g_partial[256];
__device__ int   g_csrsrc[MAXE];
__device__ float g_stats[2 * D];
__device__ float g_bnscale[D];
__device__ float g_bnshift[D];
__device__ float g_psum[MAXG * D];
__device__ int   g_pmax[MAXG * D];
__device__ int   g_pcnt[MAXG];

// ================= CSR build =================
__global__ void hist_kernel(const int* __restrict__ dst, int* __restrict__ deg, int nE)
{
    int e = blockIdx.x * blockDim.x + threadIdx.x;
    if (e < nE) atomicAdd(&deg[dst[e]], 1);
}

#define SCAN_B 1024
__global__ void scan1_kernel(const int* __restrict__ deg, int* __restrict__ rowptr,
                             int* __restrict__ partial, int n)
{
    __shared__ int sh[SCAN_B];
    int i = blockIdx.x * SCAN_B + threadIdx.x;
    int v = (i < n) ? deg[i] : 0;
    sh[threadIdx.x] = v;
    __syncthreads();
    for (int o = 1; o < SCAN_B; o <<= 1) {
        int t = (threadIdx.x >= o) ? sh[threadIdx.x - o] : 0;
        __syncthreads();
        sh[threadIdx.x] += t;
        __syncthreads();
    }
    if (i < n) rowptr[i] = sh[threadIdx.x] - v;
    if (threadIdx.x == SCAN_B - 1) partial[blockIdx.x] = sh[SCAN_B - 1];
}

__global__ void scan2_kernel(int* __restrict__ partial, int nb)
{
    if (threadIdx.x == 0) {
        int acc = 0;
        for (int i = 0; i < nb; i++) { int t = partial[i]; partial[i] = acc; acc += t; }
        partial[nb] = acc;
    }
}

__global__ void scan3_kernel(int* __restrict__ rowptr, const int* __restrict__ partial,
                             int n, int nb)
{
    int i = blockIdx.x * SCAN_B + threadIdx.x;
    if (i < n) rowptr[i] += partial[blockIdx.x];
    if (i == 0) rowptr[n] = partial[nb];
}

__global__ void fill_kernel(const int* __restrict__ src, const int* __restrict__ dst,
                            int* __restrict__ cursor, int* __restrict__ csrsrc, int nE)
{
    int e = blockIdx.x * blockDim.x + threadIdx.x;
    if (e >= nE) return;
    int p = atomicAdd(&cursor[dst[e]], 1);
    csrsrc[p] = src[e];
}

__global__ void cnt_kernel(const int* __restrict__ batch, int* __restrict__ pcnt, int n)
{
    int i = blockIdx.x * blockDim.x + threadIdx.x;
    if (i < n) atomicAdd(&pcnt[batch[i]], 1);
}

__global__ void x2h_kernel(const float* __restrict__ x, __half* __restrict__ o, int n2)
{
    int i = blockIdx.x * blockDim.x + threadIdx.x;
    if (i >= n2) return;
    float2 f = reinterpret_cast<const float2*>(x)[i];
    reinterpret_cast<__half2*>(o)[i] = __floats2half2_rn(f.x, f.y);
}

// ================= gather v2: warp/node, half-warp per edge, LDG.128 rows =========
// z_i = scale*(h_i + sum_j h_j) + (1+deg)*shift     (scale=1, shift=0 when !apply_bn)
__global__ __launch_bounds__(256) void gather16_kernel(
    const __half* __restrict__ h,
    const int* __restrict__ rowptr,
    const int* __restrict__ csrsrc,
    __half* __restrict__ z, int n, int apply_bn)
{
    __shared__ float s_scale[128], s_shift[128];
    if (apply_bn) {
        if (threadIdx.x < 128)      s_scale[threadIdx.x] = g_bnscale[threadIdx.x];
        else                        s_shift[threadIdx.x - 128] = g_bnshift[threadIdx.x - 128];
        __syncthreads();
    }
    int node = (blockIdx.x * blockDim.x + threadIdx.x) >> 5;
    int lane = threadIdx.x & 31;
    int hf   = lane >> 4;
    int sl   = lane & 15;
    if (node >= n) return;
    int beg = rowptr[node], end = rowptr[node + 1];

    const uint4* h4 = reinterpret_cast<const uint4*>(h);   // 16 uint4 per row

    // fp32 accumulators over this lane's 8 features; half 0 starts with self row
    float f[8];
    {
        uint4 sv = h4[(size_t)node * 16 + sl];
        const __half2* p = reinterpret_cast<const __half2*>(&sv);
        if (hf == 0) {
#pragma unroll
            for (int k = 0; k < 4; k++) {
                float2 t = __half22float2(p[k]);
                f[2 * k] = t.x; f[2 * k + 1] = t.y;
            }
        } else {
#pragma unroll
            for (int k = 0; k < 8; k++) f[k] = 0.f;
        }
    }

    const __half2 h2z = __float2half2_rn(0.f);

    for (int e0 = beg; e0 < end; e0 += 32) {
        int cnt = end - e0; if (cnt > 32) cnt = 32;
        int li = lane < cnt ? lane : cnt - 1;
        int s = csrsrc[e0 + li];

        __half2 ha[4], hb[4];
#pragma unroll
        for (int k = 0; k < 4; k++) { ha[k] = h2z; hb[k] = h2z; }

        int j = 0;
        for (; j + 4 <= cnt; j += 4) {                 // 4 edges per iteration
            int sjA = __shfl_sync(0xffffffffu, s, j + hf);
            int sjB = __shfl_sync(0xffffffffu, s, j + 2 + hf);
            uint4 va = h4[(size_t)sjA * 16 + sl];
            uint4 vb = h4[(size_t)sjB * 16 + sl];
            const __half2* pa = reinterpret_cast<const __half2*>(&va);
            const __half2* pb = reinterpret_cast<const __half2*>(&vb);
#pragma unroll
            for (int k = 0; k < 4; k++) {
                ha[k] = __hadd2(ha[k], pa[k]);
                hb[k] = __hadd2(hb[k], pb[k]);
            }
        }
        for (; j < cnt; j += 2) {                      // tail (up to 3 edges)
            int idx = j + hf;
            bool ok = idx < cnt;
            int sj = __shfl_sync(0xffffffffu, s, ok ? idx : 0);
            if (ok) {
                uint4 va = h4[(size_t)sj * 16 + sl];
                const __half2* pa = reinterpret_cast<const __half2*>(&va);
#pragma unroll
                for (int k = 0; k < 4; k++) ha[k] = __hadd2(ha[k], pa[k]);
            }
        }
        // flush chunk (each half2 acc held <= 8 fp16 adds)
#pragma unroll
        for (int k = 0; k < 4; k++) {
            float2 t0 = __half22float2(ha[k]);
            float2 t1 = __half22float2(hb[k]);
            f[2 * k]     += t0.x + t1.x;
            f[2 * k + 1] += t0.y + t1.y;
        }
    }

    // combine halves
#pragma unroll
    for (int k = 0; k < 8; k++) f[k] += __shfl_xor_sync(0xffffffffu, f[k], 16);

    if (hf == 0) {
        if (apply_bn) {
            float m = 1.f + (float)(end - beg);
            int jb = sl * 8;
#pragma unroll
            for (int k = 0; k < 8; k++)
                f[k] = fmaf(f[k], s_scale[jb + k], m * s_shift[jb + k]);
        }
        uint4 out;
        __half2* o = reinterpret_cast<__half2*>(&out);
#pragma unroll
        for (int k = 0; k < 4; k++) o[k] = __floats2half2_rn(f[2 * k], f[2 * k + 1]);
        reinterpret_cast<uint4*>(z)[(size_t)node * 16 + sl] = out;
    }
}

// ================= tf32 tensor-core fused MLP =================
__device__ __forceinline__ float f2tf32(float x)
{
    unsigned int u;
    asm("cvt.rna.tf32.f32 %0, %1;" : "=r"(u) : "f"(x));
    return __uint_as_float(u);
}

__device__ __forceinline__ void mma_tf32(float* c, unsigned int a0, unsigned int a1,
                                         unsigned int a2, unsigned int a3,
                                         unsigned int b0, unsigned int b1)
{
    asm volatile("mma.sync.aligned.m16n8k8.row.col.f32.tf32.tf32.f32 "
                 "{%0,%1,%2,%3}, {%4,%5,%6,%7}, {%8,%9}, {%0,%1,%2,%3};"
                 : "+f"(c[0]), "+f"(c[1]), "+f"(c[2]), "+f"(c[3])
                 : "r"(a0), "r"(a1), "r"(a2), "r"(a3), "r"(b0), "r"(b1));
}

// store W column n at s_w[k*SWS + (n&7)*16 + (n>>3)]  (thread's 16 nt values contiguous)
__device__ __forceinline__ void stash_w(float* s_w, int r, int c, float4 v)
{
    float* base = s_w + r * SWS;
    base[((c + 0) & 7) * 16 + ((c + 0) >> 3)] = f2tf32(v.x);
    base[((c + 1) & 7) * 16 + ((c + 1) >> 3)] = f2tf32(v.y);
    base[((c + 2) & 7) * 16 + ((c + 2) >> 3)] = f2tf32(v.z);
    base[((c + 3) & 7) * 16 + ((c + 3) >> 3)] = f2tf32(v.w);
}

// mode 0: write h16 out + BN stats.  mode 2: fused mean/max pooling, no h out.
__global__ __launch_bounds__(256, 1) void mlp_tc_kernel(
    const __half* __restrict__ z,
    const float* __restrict__ W1, const float* __restrict__ b1,
    const float* __restrict__ W2, const float* __restrict__ b2,
    __half* __restrict__ hout, float* __restrict__ stats,
    const int* __restrict__ batch, float* __restrict__ psum, int* __restrict__ pmax,
    int n, int mode)
{
    extern __shared__ float sm[];
    float* s_z  = sm;                       // [128][SZS]
    float* s_w  = sm + 128 * SZS;           // [128][SWS]  layout [k][g*16+nt]
    float* s_b1 = sm + 128 * SZS + 128 * SWS;
    float* s_b2 = s_b1 + 128;
    float* s_st = s_b2 + 128;               // [256] sum / sumsq

    int tid  = threadIdx.x;
    int w    = tid >> 5;
    int lane = tid & 31;
    int g    = lane >> 2;       // 0..7
    int q    = lane & 3;        // 0..3
    int base = blockIdx.x * 128;
    int cnt  = n - base; if (cnt > 128) cnt = 128;

    if (tid < 128)      s_b1[tid] = b1[tid];
    else                s_b2[tid - 128] = b2[tid - 128];
    if (tid < 256)      s_st[tid] = 0.f;

    // load Z tile (fp16 -> fp32 widening is exact; fp16 mantissa fits tf32)
    const uint2* z2 = reinterpret_cast<const uint2*>(z);
    for (int i = tid; i < 128 * 32; i += 256) {
        int r = i >> 5, c = i & 31;
        uint2 u = (r < cnt) ? z2[(size_t)(base + r) * 32 + c] : make_uint2(0u, 0u);
        float2 f0 = __half22float2(*reinterpret_cast<__half2*>(&u.x));
        float2 f1 = __half22float2(*reinterpret_cast<__half2*>(&u.y));
        *reinterpret_cast<float4*>(s_z + r * SZS + c * 4) = make_float4(f0.x, f0.y, f1.x, f1.y);
    }
    // load W1 into [k][g*16+nt] layout
    const float4* w4 = reinterpret_cast<const float4*>(W1);
    for (int i = tid; i < 128 * 32; i += 256) {
        int r = i >> 5, c4 = i & 31;
        stash_w(s_w, r, c4 * 4, w4[(size_t)r * 32 + c4]);
    }
    __syncthreads();

    int row0 = w * 16 + g;

    // ---- GEMM1: T = relu(Z @ W1 + b1) ----
    float acc[16][4];
#pragma unroll
    for (int nt = 0; nt < 16; nt++) {
        float bv0 = s_b1[nt * 8 + 2 * q], bv1 = s_b1[nt * 8 + 2 * q + 1];
        acc[nt][0] = bv0; acc[nt][1] = bv1; acc[nt][2] = bv0; acc[nt][3] = bv1;
    }
#pragma unroll
    for (int k8 = 0; k8 < 16; k8++) {
        int kc = k8 * 8 + q;
        unsigned int a0 = __float_as_uint(s_z[row0 * SZS + kc]);
        unsigned int a1 = __float_as_uint(s_z[(row0 + 8) * SZS + kc]);
        unsigned int a2 = __float_as_uint(s_z[row0 * SZS + kc + 4]);
        unsigned int a3 = __float_as_uint(s_z[(row0 + 8) * SZS + kc + 4]);
        float B0[16], B1[16];
        const float* r0p = s_w + kc * SWS + g * 16;
        const float* r1p = s_w + (kc + 4) * SWS + g * 16;
        *reinterpret_cast<float4*>(&B0[0])  = *reinterpret_cast<const float4*>(r0p + 0);
        *reinterpret_cast<float4*>(&B0[4])  = *reinterpret_cast<const float4*>(r0p + 4);
        *reinterpret_cast<float4*>(&B0[8])  = *reinterpret_cast<const float4*>(r0p + 8);
        *reinterpret_cast<float4*>(&B0[12]) = *reinterpret_cast<const float4*>(r0p + 12);
        *reinterpret_cast<float4*>(&B1[0])  = *reinterpret_cast<const float4*>(r1p + 0);
        *reinterpret_cast<float4*>(&B1[4])  = *reinterpret_cast<const float4*>(r1p + 4);
        *reinterpret_cast<float4*>(&B1[8])  = *reinterpret_cast<const float4*>(r1p + 8);
        *reinterpret_cast<float4*>(&B1[12]) = *reinterpret_cast<const float4*>(r1p + 12);
#pragma unroll
        for (int nt = 0; nt < 16; nt++)
            mma_tf32(acc[nt], a0, a1, a2, a3,
                     __float_as_uint(B0[nt]), __float_as_uint(B1[nt]));
    }
    __syncthreads();

    // store relu(T) as tf32 into freed s_z; load W2
#pragma unroll
    for (int nt = 0; nt < 16; nt++) {
        int col = nt * 8 + 2 * q;
        float2 v0 = make_float2(f2tf32(fmaxf(acc[nt][0], 0.f)), f2tf32(fmaxf(acc[nt][1], 0.f)));
        float2 v1 = make_float2(f2tf32(fmaxf(acc[nt][2], 0.f)), f2tf32(fmaxf(acc[nt][3], 0.f)));
        *reinterpret_cast<float2*>(s_z + row0 * SZS + col)       = v0;
        *reinterpret_cast<float2*>(s_z + (row0 + 8) * SZS + col) = v1;
    }
    const float4* w24 = reinterpret_cast<const float4*>(W2);
    for (int i = tid; i < 128 * 32; i += 256) {
        int r = i >> 5, c4 = i & 31;
        stash_w(s_w, r, c4 * 4, w24[(size_t)r * 32 + c4]);
    }
    __syncthreads();

    // ---- GEMM2: H = relu(T @ W2 + b2) ----
#pragma unroll
    for (int nt = 0; nt < 16; nt++) {
        float bv0 = s_b2[nt * 8 + 2 * q], bv1 = s_b2[nt * 8 + 2 * q + 1];
        acc[nt][0] = bv0; acc[nt][1] = bv1; acc[nt][2] = bv0; acc[nt][3] = bv1;
    }
#pragma unroll
    for (int k8 = 0; k8 < 16; k8++) {
        int kc = k8 * 8 + q;
        unsigned int a0 = __float_as_uint(s_z[row0 * SZS + kc]);
        unsigned int a1 = __float_as_uint(s_z[(row0 + 8) * SZS + kc]);
        unsigned int a2 = __float_as_uint(s_z[row0 * SZS + kc + 4]);
        unsigned int a3 = __float_as_uint(s_z[(row0 + 8) * SZS + kc + 4]);
        float B0[16], B1[16];
        const float* r0p = s_w + kc * SWS + g * 16;
        const float* r1p = s_w + (kc + 4) * SWS + g * 16;
        *reinterpret_cast<float4*>(&B0[0])  = *reinterpret_cast<const float4*>(r0p + 0);
        *reinterpret_cast<float4*>(&B0[4])  = *reinterpret_cast<const float4*>(r0p + 4);
        *reinterpret_cast<float4*>(&B0[8])  = *reinterpret_cast<const float4*>(r0p + 8);
        *reinterpret_cast<float4*>(&B0[12]) = *reinterpret_cast<const float4*>(r0p + 12);
        *reinterpret_cast<float4*>(&B1[0])  = *reinterpret_cast<const float4*>(r1p + 0);
        *reinterpret_cast<float4*>(&B1[4])  = *reinterpret_cast<const float4*>(r1p + 4);
        *reinterpret_cast<float4*>(&B1[8])  = *reinterpret_cast<const float4*>(r1p + 8);
        *reinterpret_cast<float4*>(&B1[12]) = *reinterpret_cast<const float4*>(r1p + 12);
#pragma unroll
        for (int nt = 0; nt < 16; nt++)
            mma_tf32(acc[nt], a0, a1, a2, a3,
                     __float_as_uint(B0[nt]), __float_as_uint(B1[nt]));
    }

    bool ok0 = (row0 < cnt), ok1 = (row0 + 8 < cnt);

    if (mode != 2) {
        __half2* o0 = reinterpret_cast<__half2*>(hout + (size_t)(base + row0) * 128);
        __half2* o1 = reinterpret_cast<__half2*>(hout + (size_t)(base + row0 + 8) * 128);
#pragma unroll
        for (int nt = 0; nt < 16; nt++) {
            int c0 = nt * 8 + 2 * q;
            float v00 = fmaxf(acc[nt][0], 0.f), v01 = fmaxf(acc[nt][1], 0.f);
            float v10 = fmaxf(acc[nt][2], 0.f), v11 = fmaxf(acc[nt][3], 0.f);
            if (ok0) o0[nt * 4 + q] = __floats2half2_rn(v00, v01);
            if (ok1) o1[nt * 4 + q] = __floats2half2_rn(v10, v11);
            float a00 = ok0 ? v00 : 0.f, a01 = ok0 ? v01 : 0.f;
            float a10 = ok1 ? v10 : 0.f, a11 = ok1 ? v11 : 0.f;
            float s0 = a00 + a10, s1 = a01 + a11;
            float q0 = a00 * a00 + a10 * a10, q1 = a01 * a01 + a11 * a11;
#pragma unroll
            for (int m = 4; m <= 16; m <<= 1) {
                s0 += __shfl_xor_sync(0xffffffffu, s0, m);
                s1 += __shfl_xor_sync(0xffffffffu, s1, m);
                q0 += __shfl_xor_sync(0xffffffffu, q0, m);
                q1 += __shfl_xor_sync(0xffffffffu, q1, m);
            }
            if (g == 0) {
                atomicAdd(&s_st[c0],           s0);
                atomicAdd(&s_st[c0 + 1],       s1);
                atomicAdd(&s_st[128 + c0],     q0);
                atomicAdd(&s_st[128 + c0 + 1], q1);
            }
        }
        __syncthreads();
        if (tid < 256) atomicAdd(&stats[tid], s_st[tid]);
    } else {
        int b0 = ok0 ? batch[base + row0] : 0;
        int b1i = ok1 ? batch[base + row0 + 8] : 0;
#pragma unroll
        for (int nt = 0; nt < 16; nt++) {
            int c0 = nt * 8 + 2 * q;
            float v00 = fmaxf(acc[nt][0], 0.f), v01 = fmaxf(acc[nt][1], 0.f);
            float v10 = fmaxf(acc[nt][2], 0.f), v11 = fmaxf(acc[nt][3], 0.f);
            if (ok0) {
                atomicAdd(&psum[b0 * D + c0],     v00);
                atomicAdd(&psum[b0 * D + c0 + 1], v01);
                atomicMax(&pmax[b0 * D + c0],     __float_as_int(v00));
                atomicMax(&pmax[b0 * D + c0 + 1], __float_as_int(v01));
            }
            if (ok1) {
                atomicAdd(&psum[b1i * D + c0],     v10);
                atomicAdd(&psum[b1i * D + c0 + 1], v11);
                atomicMax(&pmax[b1i * D + c0],     __float_as_int(v10));
                atomicMax(&pmax[b1i * D + c0 + 1], __float_as_int(v11));
            }
        }
    }
}

__global__ void bn_scale_kernel(const float* __restrict__ stats,
                                const float* __restrict__ gamma,
                                const float* __restrict__ beta, float inv_n)
{
    int j = threadIdx.x;
    float mu = stats[j] * inv_n;
    float var = stats[D + j] * inv_n - mu * mu;
    float sc = gamma[j] * rsqrtf(var + 1e-5f);
    g_bnscale[j] = sc;
    g_bnshift[j] = beta[j] - mu * sc;
}

// ================= final head =================
__device__ __forceinline__ float breduce128(float v, float* s4)
{
    int lane = threadIdx.x & 31, w = threadIdx.x >> 5;
#pragma unroll
    for (int o = 16; o; o >>= 1) v += __shfl_down_sync(0xffffffffu, v, o);
    if (lane == 0) s4[w] = v;
    __syncthreads();
    float r = s4[0] + s4[1] + s4[2] + s4[3];
    __syncthreads();
    return r;
}

__global__ __launch_bounds__(128) void final_kernel(
    const float* __restrict__ psum, const int* __restrict__ pmax,
    const int* __restrict__ pcnt,
    const float* __restrict__ Wg, const float* __restrict__ bg,
    const float* __restrict__ pb, const float* __restrict__ pm,
    const int* __restrict__ y, float* __restrict__ out)
{
    __shared__ float s_gx[2 * D];
    __shared__ float s4[4];
    int g = blockIdx.x, j = threadIdx.x;

    float cntf = fmaxf((float)pcnt[g], 1.f);
    s_gx[j]     = psum[g * D + j] / cntf;
    s_gx[D + j] = __int_as_float(pmax[g * D + j]);
    __syncthreads();

    float rep = bg[j];
#pragma unroll
    for (int k = 0; k < 2 * D; k++) rep = fmaf(s_gx[k], Wg[k * D + j], rep);

    float nrm = breduce128(rep * rep, s4);
    float feat = rep / fmaxf(sqrtf(nrm), 1e-12f);

    float pbj = pb[j], pmj = pm[j];
    float nb = breduce128(pbj * pbj, s4);
    float nm = breduce128(pmj * pmj, s4);
    pbj /= fmaxf(sqrtf(nb), 1e-12f);
    pmj /= fmaxf(sqrtf(nm), 1e-12f);

    float cb = breduce128(feat * pbj, s4);
    float cm = breduce128(feat * pmj, s4);

    if (j == 0) {
        bool mal = (y[g] == 1);
        float a = mal ? cb * cb : (1.f - cb) * (1.f - cb);
        float b = mal ? (1.f - cm) * (1.f - cm) : cm * cm;
        atomicAdd(out, a + b);
    }
}

// ================= host =================
extern "C" void kernel_launch(void* const* d_in, const int* in_sizes, int n_in,
                              void* d_out, int out_size)
{
    const float* x   = (const float*)d_in[0];
    const int* ei    = (const int*)d_in[1];
    const int* batch = (const int*)d_in[2];
    const int* y     = (const int*)d_in[3];
    const float* W1  = (const float*)d_in[4];
    const float* b1  = (const float*)d_in[5];
    const float* W2  = (const float*)d_in[6];
    const float* b2  = (const float*)d_in[7];
    const float* bng = (const float*)d_in[8];
    const float* bnb = (const float*)d_in[9];
    const float* Wg  = (const float*)d_in[10];
    const float* bg  = (const float*)d_in[11];
    const float* pb  = (const float*)d_in[12];
    const float* pm  = (const float*)d_in[13];

    int n  = in_sizes[0] / D;
    int nE = in_sizes[1] / 2;
    int G  = in_sizes[3];
    const int* src = ei;
    const int* dst = ei + nE;

    __half *h16A, *h16B, *x16, *z16;
    float *stats;
    int *rowptr, *cursor, *partial, *csrsrc;
    void *psum, *pmax, *pcnt;
    cudaGetSymbolAddress((void**)&h16A, g_h16A);
    cudaGetSymbolAddress((void**)&h16B, g_h16B);
    cudaGetSymbolAddress((void**)&x16, g_x16);
    cudaGetSymbolAddress((void**)&z16, g_z16);
    cudaGetSymbolAddress((void**)&stats, g_stats);
    cudaGetSymbolAddress((void**)&rowptr, g_rowptr);
    cudaGetSymbolAddress((void**)&cursor, g_cursor);
    cudaGetSymbolAddress((void**)&partial, g_partial);
    cudaGetSymbolAddress((void**)&csrsrc, g_csrsrc);
    cudaGetSymbolAddress(&psum, g_psum);
    cudaGetSymbolAddress(&pmax, g_pmax);
    cudaGetSymbolAddress(&pcnt, g_pcnt);

    cudaFuncSetAttribute(mlp_tc_kernel, cudaFuncAttributeMaxDynamicSharedMemorySize, MLP_SMEM);

    // ---- CSR build + prep (once) ----
    int nb = (n + SCAN_B - 1) / SCAN_B;
    cudaMemsetAsync(cursor, 0, (n + 1) * sizeof(int));
    hist_kernel<<<(nE + 255) / 256, 256>>>(dst, cursor, nE);
    scan1_kernel<<<nb, SCAN_B>>>(cursor, rowptr, partial, n);
    scan2_kernel<<<1, 32>>>(partial, nb);
    scan3_kernel<<<nb, SCAN_B>>>(rowptr, partial, n, nb);
    cudaMemcpyAsync(cursor, rowptr, n * sizeof(int), cudaMemcpyDeviceToDevice);
    fill_kernel<<<(nE + 255) / 256, 256>>>(src, dst, cursor, csrsrc, nE);

    cudaMemsetAsync(pcnt, 0, (size_t)G * sizeof(int));
    cudaMemsetAsync(psum, 0, (size_t)G * D * sizeof(float));
    cudaMemsetAsync(pmax, 0, (size_t)G * D * sizeof(int));
    cnt_kernel<<<(n + 255) / 256, 256>>>(batch, (int*)pcnt, n);
    x2h_kernel<<<(n * 64 + 255) / 256, 256>>>(x, x16, n * 64);

    // ---- layers ----
    const __half* cur = x16;
    __half* nxt = h16A;
    int mlpBlocks = (n + 127) / 128;
    int gthBlocks = (n * 32 + 255) / 256;

    for (int l = 0; l < 3; l++) {
        gather16_kernel<<<gthBlocks, 256>>>(cur, rowptr, csrsrc, z16, n, l > 0 ? 1 : 0);
        if (l < 2) {
            cudaMemsetAsync(stats, 0, 2 * D * sizeof(float));
            mlp_tc_kernel<<<mlpBlocks, 256, MLP_SMEM>>>(z16,
                W1 + l * D * D, b1 + l * D, W2 + l * D * D, b2 + l * D,
                nxt, stats, batch, (float*)psum, (int*)pmax, n, 0);
            bn_scale_kernel<<<1, D>>>(stats, bng + l * D, bnb + l * D, 1.f / (float)n);
            cur = nxt;
            nxt = (l == 0) ? h16B : h16A;
        } else {
            mlp_tc_kernel<<<mlpBlocks, 256, MLP_SMEM>>>(z16,
                W1 + l * D * D, b1 + l * D, W2 + l * D * D, b2 + l * D,
                nullptr, stats, batch, (float*)psum, (int*)pmax, n, 2);
        }
    }

    cudaMemsetAsync(d_out, 0, sizeof(float));
    final_kernel<<<G, 128>>>((const float*)psum, (const int*)pmax, (const int*)pcnt,
                             Wg, bg, pb, pm, y, (float*)d_out);
}

// round 9
// speedup vs baseline: 3.4065x; 1.4592x over previous
#include <cuda_runtime.h>
#include <cuda_fp16.h>
#include <stdint.h>
#include <math.h>

#define D 128
#define MAXN 100000
#define MAXE 1600000
#define MAXG 512

#define SZH 68            // half2 stride of A rows in smem
#define SWH 132           // half2 stride of B k2-rows in smem (and gmem image)
#define WIMG (64 * SWH)   // half2 words per weight-matrix image
#define MLP_SMEM ((128 * SZH + 64 * SWH + 256 + 256) * 4)

// ---------------- scratch ----------------
__device__ __half g_h16A[MAXN * D];
__device__ __half g_h16B[MAXN * D];
__device__ __half g_x16[MAXN * D];
__device__ __half g_z16[MAXN * D];
__device__ unsigned g_wt[3 * 2 * WIMG];   // fp16 weight images, smem-ready layout
__device__ int   g_rowptr[MAXN + 1];
__device__ int   g_cursor[MAXN + 1];
__device__ int   g_partial[256];
__device__ int   g_csrsrc[MAXE];
__device__ float g_stats[2 * D];
__device__ float g_bnscale[D];
__device__ float g_bnshift[D];
__device__ float g_psum[MAXG * D];
__device__ int   g_pmax[MAXG * D];
__device__ int   g_pcnt[MAXG];

// ================= CSR build =================
__global__ void hist_kernel(const int* __restrict__ dst, int* __restrict__ deg, int nE)
{
    int e = blockIdx.x * blockDim.x + threadIdx.x;
    if (e < nE) atomicAdd(&deg[dst[e]], 1);
}

#define SCAN_B 1024
__global__ void scan1_kernel(const int* __restrict__ deg, int* __restrict__ rowptr,
                             int* __restrict__ partial, int n)
{
    __shared__ int sh[SCAN_B];
    int i = blockIdx.x * SCAN_B + threadIdx.x;
    int v = (i < n) ? deg[i] : 0;
    sh[threadIdx.x] = v;
    __syncthreads();
    for (int o = 1; o < SCAN_B; o <<= 1) {
        int t = (threadIdx.x >= o) ? sh[threadIdx.x - o] : 0;
        __syncthreads();
        sh[threadIdx.x] += t;
        __syncthreads();
    }
    if (i < n) rowptr[i] = sh[threadIdx.x] - v;
    if (threadIdx.x == SCAN_B - 1) partial[blockIdx.x] = sh[SCAN_B - 1];
}

__global__ void scan2_kernel(int* __restrict__ partial, int nb)
{
    if (threadIdx.x == 0) {
        int acc = 0;
        for (int i = 0; i < nb; i++) { int t = partial[i]; partial[i] = acc; acc += t; }
        partial[nb] = acc;
    }
}

__global__ void scan3_kernel(int* __restrict__ rowptr, const int* __restrict__ partial,
                             int n, int nb)
{
    int i = blockIdx.x * SCAN_B + threadIdx.x;
    if (i < n) rowptr[i] += partial[blockIdx.x];
    if (i == 0) rowptr[n] = partial[nb];
}

__global__ void fill_kernel(const int* __restrict__ src, const int* __restrict__ dst,
                            int* __restrict__ cursor, int* __restrict__ csrsrc, int nE)
{
    int e = blockIdx.x * blockDim.x + threadIdx.x;
    if (e >= nE) return;
    int p = atomicAdd(&cursor[dst[e]], 1);
    csrsrc[p] = src[e];
}

__global__ void cnt_kernel(const int* __restrict__ batch, int* __restrict__ pcnt, int n)
{
    int i = blockIdx.x * blockDim.x + threadIdx.x;
    if (i < n) atomicAdd(&pcnt[batch[i]], 1);
}

__global__ void x2h_kernel(const float* __restrict__ x, __half* __restrict__ o, int n2)
{
    int i = blockIdx.x * blockDim.x + threadIdx.x;
    if (i >= n2) return;
    float2 f = reinterpret_cast<const float2*>(x)[i];
    reinterpret_cast<__half2*>(o)[i] = __floats2half2_rn(f.x, f.y);
}

// build fp16 weight images: img[(l,m)][k2*SWH + perm(n)] = half2(W[2k2][n], W[2k2+1][n])
__global__ void wprep_kernel(const float* __restrict__ W1, const float* __restrict__ W2)
{
    int i = blockIdx.x * blockDim.x + threadIdx.x;    // 3*2*64*128
    if (i >= 3 * 2 * 64 * 128) return;
    int n  = i & 127;
    int k2 = (i >> 7) & 63;
    int m  = (i >> 13) & 1;
    int l  = i >> 14;
    const float* W = (m == 0 ? W1 : W2) + l * D * D;
    __half2 v = __floats2half2_rn(W[(2 * k2) * D + n], W[(2 * k2 + 1) * D + n]);
    int perm = (n & 7) * 16 + (n >> 3);
    g_wt[((l * 2 + m) * 64 + k2) * SWH + perm] = *reinterpret_cast<unsigned*>(&v);
}

// ================= gather: warp/node, half-warp per edge =================
__global__ __launch_bounds__(256) void gather16_kernel(
    const __half* __restrict__ h,
    const int* __restrict__ rowptr,
    const int* __restrict__ csrsrc,
    __half* __restrict__ z, int n, int apply_bn)
{
    __shared__ float s_scale[128], s_shift[128];
    if (apply_bn) {
        if (threadIdx.x < 128)      s_scale[threadIdx.x] = g_bnscale[threadIdx.x];
        else                        s_shift[threadIdx.x - 128] = g_bnshift[threadIdx.x - 128];
        __syncthreads();
    }
    int node = (blockIdx.x * blockDim.x + threadIdx.x) >> 5;
    int lane = threadIdx.x & 31;
    int hf   = lane >> 4;
    int sl   = lane & 15;
    if (node >= n) return;
    int beg = rowptr[node], end = rowptr[node + 1];

    const uint4* h4 = reinterpret_cast<const uint4*>(h);

    float f[8];
    {
        uint4 sv = h4[(size_t)node * 16 + sl];
        const __half2* p = reinterpret_cast<const __half2*>(&sv);
        if (hf == 0) {
#pragma unroll
            for (int k = 0; k < 4; k++) {
                float2 t = __half22float2(p[k]);
                f[2 * k] = t.x; f[2 * k + 1] = t.y;
            }
        } else {
#pragma unroll
            for (int k = 0; k < 8; k++) f[k] = 0.f;
        }
    }

    const __half2 h2z = __float2half2_rn(0.f);

    for (int e0 = beg; e0 < end; e0 += 32) {
        int cnt = end - e0; if (cnt > 32) cnt = 32;
        int li = lane < cnt ? lane : cnt - 1;
        int s = csrsrc[e0 + li];

        __half2 ha[4], hb[4];
#pragma unroll
        for (int k = 0; k < 4; k++) { ha[k] = h2z; hb[k] = h2z; }

        int j = 0;
        for (; j + 4 <= cnt; j += 4) {
            int sjA = __shfl_sync(0xffffffffu, s, j + hf);
            int sjB = __shfl_sync(0xffffffffu, s, j + 2 + hf);
            uint4 va = h4[(size_t)sjA * 16 + sl];
            uint4 vb = h4[(size_t)sjB * 16 + sl];
            const __half2* pa = reinterpret_cast<const __half2*>(&va);
            const __half2* pb = reinterpret_cast<const __half2*>(&vb);
#pragma unroll
            for (int k = 0; k < 4; k++) {
                ha[k] = __hadd2(ha[k], pa[k]);
                hb[k] = __hadd2(hb[k], pb[k]);
            }
        }
        for (; j < cnt; j += 2) {
            int idx = j + hf;
            bool ok = idx < cnt;
            int sj = __shfl_sync(0xffffffffu, s, ok ? idx : 0);
            if (ok) {
                uint4 va = h4[(size_t)sj * 16 + sl];
                const __half2* pa = reinterpret_cast<const __half2*>(&va);
#pragma unroll
                for (int k = 0; k < 4; k++) ha[k] = __hadd2(ha[k], pa[k]);
            }
        }
#pragma unroll
        for (int k = 0; k < 4; k++) {
            float2 t0 = __half22float2(ha[k]);
            float2 t1 = __half22float2(hb[k]);
            f[2 * k]     += t0.x + t1.x;
            f[2 * k + 1] += t0.y + t1.y;
        }
    }

#pragma unroll
    for (int k = 0; k < 8; k++) f[k] += __shfl_xor_sync(0xffffffffu, f[k], 16);

    if (hf == 0) {
        if (apply_bn) {
            float m = 1.f + (float)(end - beg);
            int jb = sl * 8;
#pragma unroll
            for (int k = 0; k < 8; k++)
                f[k] = fmaf(f[k], s_scale[jb + k], m * s_shift[jb + k]);
        }
        uint4 out;
        __half2* o = reinterpret_cast<__half2*>(&out);
#pragma unroll
        for (int k = 0; k < 4; k++) o[k] = __floats2half2_rn(f[2 * k], f[2 * k + 1]);
        reinterpret_cast<uint4*>(z)[(size_t)node * 16 + sl] = out;
    }
}

// ================= fp16 tensor-core fused MLP (m16n8k16) =================
__device__ __forceinline__ void mma_f16(float* c, unsigned a0, unsigned a1,
                                        unsigned a2, unsigned a3,
                                        unsigned b0, unsigned b1)
{
    asm volatile("mma.sync.aligned.m16n8k16.row.col.f32.f16.f16.f32 "
                 "{%0,%1,%2,%3}, {%4,%5,%6,%7}, {%8,%9}, {%0,%1,%2,%3};"
                 : "+f"(c[0]), "+f"(c[1]), "+f"(c[2]), "+f"(c[3])
                 : "r"(a0), "r"(a1), "r"(a2), "r"(a3), "r"(b0), "r"(b1));
}

// mode 0: write h16 out + fused BN stats.  mode 2: fused mean/max pooling.
__global__ __launch_bounds__(256, 1) void mlp16_kernel(
    const __half* __restrict__ z,
    const unsigned* __restrict__ wimg1, const unsigned* __restrict__ wimg2,
    const float* __restrict__ b1, const float* __restrict__ b2,
    __half* __restrict__ hout, float* __restrict__ stats,
    const int* __restrict__ batch, float* __restrict__ psum, int* __restrict__ pmax,
    int n, int mode)
{
    extern __shared__ unsigned smu[];
    unsigned* s_z = smu;                               // [128][SZH] half2
    unsigned* s_w = smu + 128 * SZH;                   // [64][SWH] half2
    float* s_b1 = reinterpret_cast<float*>(smu + 128 * SZH + 64 * SWH);
    float* s_b2 = s_b1 + 128;
    float* s_st = s_b2 + 128;                          // [256] sum / sumsq

    int tid  = threadIdx.x;
    int w    = tid >> 5;
    int lane = tid & 31;
    int g    = lane >> 2;
    int q    = lane & 3;
    int base = blockIdx.x * 128;
    int cnt  = n - base; if (cnt > 128) cnt = 128;

    if (tid < 128)      s_b1[tid] = b1[tid];
    else                s_b2[tid - 128] = b2[tid - 128];
    if (tid < 256)      s_st[tid] = 0.f;

    // load Z tile (fp16, strided rows)
    const uint4* z4 = reinterpret_cast<const uint4*>(z);
#pragma unroll
    for (int it = 0; it < 8; it++) {
        int i = it * 256 + tid;
        int r = i >> 4, c8 = i & 15;
        uint4 v = (r < cnt) ? z4[(size_t)(base + r) * 16 + c8] : make_uint4(0u, 0u, 0u, 0u);
        *reinterpret_cast<uint4*>(s_z + r * SZH + c8 * 4) = v;
    }
    // load W1 image (linear copy; layout already matches)
    const uint4* w14 = reinterpret_cast<const uint4*>(wimg1);
#pragma unroll
    for (int it = 0; it < 9; it++) {
        int i = it * 256 + tid;
        if (i < WIMG / 4) reinterpret_cast<uint4*>(s_w)[i] = w14[i];
    }
    __syncthreads();

    int row0 = w * 16 + g;

    // ---- GEMM1: T = relu(Z @ W1 + b1) ----
    float acc[16][4];
#pragma unroll
    for (int nt = 0; nt < 16; nt++) {
        float bv0 = s_b1[nt * 8 + 2 * q], bv1 = s_b1[nt * 8 + 2 * q + 1];
        acc[nt][0] = bv0; acc[nt][1] = bv1; acc[nt][2] = bv0; acc[nt][3] = bv1;
    }
#pragma unroll
    for (int k8 = 0; k8 < 8; k8++) {
        int kq = k8 * 8 + q;
        unsigned a0 = s_z[row0 * SZH + kq];
        unsigned a1 = s_z[(row0 + 8) * SZH + kq];
        unsigned a2 = s_z[row0 * SZH + kq + 4];
        unsigned a3 = s_z[(row0 + 8) * SZH + kq + 4];
        unsigned B0[16], B1[16];
        const unsigned* r0p = s_w + kq * SWH + g * 16;
        const unsigned* r1p = s_w + (kq + 4) * SWH + g * 16;
        *reinterpret_cast<uint4*>(&B0[0])  = *reinterpret_cast<const uint4*>(r0p + 0);
        *reinterpret_cast<uint4*>(&B0[4])  = *reinterpret_cast<const uint4*>(r0p + 4);
        *reinterpret_cast<uint4*>(&B0[8])  = *reinterpret_cast<const uint4*>(r0p + 8);
        *reinterpret_cast<uint4*>(&B0[12]) = *reinterpret_cast<const uint4*>(r0p + 12);
        *reinterpret_cast<uint4*>(&B1[0])  = *reinterpret_cast<const uint4*>(r1p + 0);
        *reinterpret_cast<uint4*>(&B1[4])  = *reinterpret_cast<const uint4*>(r1p + 4);
        *reinterpret_cast<uint4*>(&B1[8])  = *reinterpret_cast<const uint4*>(r1p + 8);
        *reinterpret_cast<uint4*>(&B1[12]) = *reinterpret_cast<const uint4*>(r1p + 12);
#pragma unroll
        for (int nt = 0; nt < 16; nt++)
            mma_f16(acc[nt], a0, a1, a2, a3, B0[nt], B1[nt]);
    }
    __syncthreads();

    // store relu(T) as fp16 into freed s_z; load W2 image
#pragma unroll
    for (int nt = 0; nt < 16; nt++) {
        int hI = nt * 4 + q;
        __half2 v0 = __floats2half2_rn(fmaxf(acc[nt][0], 0.f), fmaxf(acc[nt][1], 0.f));
        __half2 v1 = __floats2half2_rn(fmaxf(acc[nt][2], 0.f), fmaxf(acc[nt][3], 0.f));
        s_z[row0 * SZH + hI]       = *reinterpret_cast<unsigned*>(&v0);
        s_z[(row0 + 8) * SZH + hI] = *reinterpret_cast<unsigned*>(&v1);
    }
    const uint4* w24 = reinterpret_cast<const uint4*>(wimg2);
#pragma unroll
    for (int it = 0; it < 9; it++) {
        int i = it * 256 + tid;
        if (i < WIMG / 4) reinterpret_cast<uint4*>(s_w)[i] = w24[i];
    }
    __syncthreads();

    // ---- GEMM2: H = relu(T @ W2 + b2) ----
#pragma unroll
    for (int nt = 0; nt < 16; nt++) {
        float bv0 = s_b2[nt * 8 + 2 * q], bv1 = s_b2[nt * 8 + 2 * q + 1];
        acc[nt][0] = bv0; acc[nt][1] = bv1; acc[nt][2] = bv0; acc[nt][3] = bv1;
    }
#pragma unroll
    for (int k8 = 0; k8 < 8; k8++) {
        int kq = k8 * 8 + q;
        unsigned a0 = s_z[row0 * SZH + kq];
        unsigned a1 = s_z[(row0 + 8) * SZH + kq];
        unsigned a2 = s_z[row0 * SZH + kq + 4];
        unsigned a3 = s_z[(row0 + 8) * SZH + kq + 4];
        unsigned B0[16], B1[16];
        const unsigned* r0p = s_w + kq * SWH + g * 16;
        const unsigned* r1p = s_w + (kq + 4) * SWH + g * 16;
        *reinterpret_cast<uint4*>(&B0[0])  = *reinterpret_cast<const uint4*>(r0p + 0);
        *reinterpret_cast<uint4*>(&B0[4])  = *reinterpret_cast<const uint4*>(r0p + 4);
        *reinterpret_cast<uint4*>(&B0[8])  = *reinterpret_cast<const uint4*>(r0p + 8);
        *reinterpret_cast<uint4*>(&B0[12]) = *reinterpret_cast<const uint4*>(r0p + 12);
        *reinterpret_cast<uint4*>(&B1[0])  = *reinterpret_cast<const uint4*>(r1p + 0);
        *reinterpret_cast<uint4*>(&B1[4])  = *reinterpret_cast<const uint4*>(r1p + 4);
        *reinterpret_cast<uint4*>(&B1[8])  = *reinterpret_cast<const uint4*>(r1p + 8);
        *reinterpret_cast<uint4*>(&B1[12]) = *reinterpret_cast<const uint4*>(r1p + 12);
#pragma unroll
        for (int nt = 0; nt < 16; nt++)
            mma_f16(acc[nt], a0, a1, a2, a3, B0[nt], B1[nt]);
    }

    bool ok0 = (row0 < cnt), ok1 = (row0 + 8 < cnt);

    if (mode != 2) {
        __half2* o0 = reinterpret_cast<__half2*>(hout + (size_t)(base + row0) * 128);
        __half2* o1 = reinterpret_cast<__half2*>(hout + (size_t)(base + row0 + 8) * 128);
#pragma unroll
        for (int nt = 0; nt < 16; nt++) {
            int c0 = nt * 8 + 2 * q;
            float v00 = fmaxf(acc[nt][0], 0.f), v01 = fmaxf(acc[nt][1], 0.f);
            float v10 = fmaxf(acc[nt][2], 0.f), v11 = fmaxf(acc[nt][3], 0.f);
            if (ok0) o0[nt * 4 + q] = __floats2half2_rn(v00, v01);
            if (ok1) o1[nt * 4 + q] = __floats2half2_rn(v10, v11);
            float a00 = ok0 ? v00 : 0.f, a01 = ok0 ? v01 : 0.f;
            float a10 = ok1 ? v10 : 0.f, a11 = ok1 ? v11 : 0.f;
            float s0 = a00 + a10, s1 = a01 + a11;
            float q0 = a00 * a00 + a10 * a10, q1 = a01 * a01 + a11 * a11;
#pragma unroll
            for (int m = 4; m <= 16; m <<= 1) {
                s0 += __shfl_xor_sync(0xffffffffu, s0, m);
                s1 += __shfl_xor_sync(0xffffffffu, s1, m);
                q0 += __shfl_xor_sync(0xffffffffu, q0, m);
                q1 += __shfl_xor_sync(0xffffffffu, q1, m);
            }
            if (g == 0) {
                atomicAdd(&s_st[c0],           s0);
                atomicAdd(&s_st[c0 + 1],       s1);
                atomicAdd(&s_st[128 + c0],     q0);
                atomicAdd(&s_st[128 + c0 + 1], q1);
            }
        }
        __syncthreads();
        if (tid < 256) atomicAdd(&stats[tid], s_st[tid]);
    } else {
        int b0 = ok0 ? batch[base + row0] : 0;
        int b1i = ok1 ? batch[base + row0 + 8] : 0;
#pragma unroll
        for (int nt = 0; nt < 16; nt++) {
            int c0 = nt * 8 + 2 * q;
            float v00 = fmaxf(acc[nt][0], 0.f), v01 = fmaxf(acc[nt][1], 0.f);
            float v10 = fmaxf(acc[nt][2], 0.f), v11 = fmaxf(acc[nt][3], 0.f);
            if (ok0) {
                atomicAdd(&psum[b0 * D + c0],     v00);
                atomicAdd(&psum[b0 * D + c0 + 1], v01);
                atomicMax(&pmax[b0 * D + c0],     __float_as_int(v00));
                atomicMax(&pmax[b0 * D + c0 + 1], __float_as_int(v01));
            }
            if (ok1) {
                atomicAdd(&psum[b1i * D + c0],     v10);
                atomicAdd(&psum[b1i * D + c0 + 1], v11);
                atomicMax(&pmax[b1i * D + c0],     __float_as_int(v10));
                atomicMax(&pmax[b1i * D + c0 + 1], __float_as_int(v11));
            }
        }
    }
}

__global__ void bn_scale_kernel(const float* __restrict__ stats,
                                const float* __restrict__ gamma,
                                const float* __restrict__ beta, float inv_n)
{
    int j = threadIdx.x;
    float mu = stats[j] * inv_n;
    float var = stats[D + j] * inv_n - mu * mu;
    float sc = gamma[j] * rsqrtf(var + 1e-5f);
    g_bnscale[j] = sc;
    g_bnshift[j] = beta[j] - mu * sc;
}

// ================= final head =================
__device__ __forceinline__ float breduce128(float v, float* s4)
{
    int lane = threadIdx.x & 31, w = threadIdx.x >> 5;
#pragma unroll
    for (int o = 16; o; o >>= 1) v += __shfl_down_sync(0xffffffffu, v, o);
    if (lane == 0) s4[w] = v;
    __syncthreads();
    float r = s4[0] + s4[1] + s4[2] + s4[3];
    __syncthreads();
    return r;
}

__global__ __launch_bounds__(128) void final_kernel(
    const float* __restrict__ psum, const int* __restrict__ pmax,
    const int* __restrict__ pcnt,
    const float* __restrict__ Wg, const float* __restrict__ bg,
    const float* __restrict__ pb, const float* __restrict__ pm,
    const int* __restrict__ y, float* __restrict__ out)
{
    __shared__ float s_gx[2 * D];
    __shared__ float s4[4];
    int g = blockIdx.x, j = threadIdx.x;

    float cntf = fmaxf((float)pcnt[g], 1.f);
    s_gx[j]     = psum[g * D + j] / cntf;
    s_gx[D + j] = __int_as_float(pmax[g * D + j]);
    __syncthreads();

    float rep = bg[j];
#pragma unroll
    for (int k = 0; k < 2 * D; k++) rep = fmaf(s_gx[k], Wg[k * D + j], rep);

    float nrm = breduce128(rep * rep, s4);
    float feat = rep / fmaxf(sqrtf(nrm), 1e-12f);

    float pbj = pb[j], pmj = pm[j];
    float nb = breduce128(pbj * pbj, s4);
    float nm = breduce128(pmj * pmj, s4);
    pbj /= fmaxf(sqrtf(nb), 1e-12f);
    pmj /= fmaxf(sqrtf(nm), 1e-12f);

    float cb = breduce128(feat * pbj, s4);
    float cm = breduce128(feat * pmj, s4);

    if (j == 0) {
        bool mal = (y[g] == 1);
        float a = mal ? cb * cb : (1.f - cb) * (1.f - cb);
        float b = mal ? (1.f - cm) * (1.f - cm) : cm * cm;
        atomicAdd(out, a + b);
    }
}

// ================= host =================
extern "C" void kernel_launch(void* const* d_in, const int* in_sizes, int n_in,
                              void* d_out, int out_size)
{
    const float* x   = (const float*)d_in[0];
    const int* ei    = (const int*)d_in[1];
    const int* batch = (const int*)d_in[2];
    const int* y     = (const int*)d_in[3];
    const float* W1  = (const float*)d_in[4];
    const float* b1  = (const float*)d_in[5];
    const float* W2  = (const float*)d_in[6];
    const float* b2  = (const float*)d_in[7];
    const float* bng = (const float*)d_in[8];
    const float* bnb = (const float*)d_in[9];
    const float* Wg  = (const float*)d_in[10];
    const float* bg  = (const float*)d_in[11];
    const float* pb  = (const float*)d_in[12];
    const float* pm  = (const float*)d_in[13];

    int n  = in_sizes[0] / D;
    int nE = in_sizes[1] / 2;
    int G  = in_sizes[3];
    const int* src = ei;
    const int* dst = ei + nE;

    __half *h16A, *h16B, *x16, *z16;
    unsigned* wt;
    float *stats;
    int *rowptr, *cursor, *partial, *csrsrc;
    void *psum, *pmax, *pcnt;
    cudaGetSymbolAddress((void**)&h16A, g_h16A);
    cudaGetSymbolAddress((void**)&h16B, g_h16B);
    cudaGetSymbolAddress((void**)&x16, g_x16);
    cudaGetSymbolAddress((void**)&z16, g_z16);
    cudaGetSymbolAddress((void**)&wt, g_wt);
    cudaGetSymbolAddress((void**)&stats, g_stats);
    cudaGetSymbolAddress((void**)&rowptr, g_rowptr);
    cudaGetSymbolAddress((void**)&cursor, g_cursor);
    cudaGetSymbolAddress((void**)&partial, g_partial);
    cudaGetSymbolAddress((void**)&csrsrc, g_csrsrc);
    cudaGetSymbolAddress(&psum, g_psum);
    cudaGetSymbolAddress(&pmax, g_pmax);
    cudaGetSymbolAddress(&pcnt, g_pcnt);

    cudaFuncSetAttribute(mlp16_kernel, cudaFuncAttributeMaxDynamicSharedMemorySize, MLP_SMEM);

    // ---- CSR build + prep (once) ----
    int nb = (n + SCAN_B - 1) / SCAN_B;
    cudaMemsetAsync(cursor, 0, (n + 1) * sizeof(int));
    hist_kernel<<<(nE + 255) / 256, 256>>>(dst, cursor, nE);
    scan1_kernel<<<nb, SCAN_B>>>(cursor, rowptr, partial, n);
    scan2_kernel<<<1, 32>>>(partial, nb);
    scan3_kernel<<<nb, SCAN_B>>>(rowptr, partial, n, nb);
    cudaMemcpyAsync(cursor, rowptr, n * sizeof(int), cudaMemcpyDeviceToDevice);
    fill_kernel<<<(nE + 255) / 256, 256>>>(src, dst, cursor, csrsrc, nE);

    cudaMemsetAsync(pcnt, 0, (size_t)G * sizeof(int));
    cudaMemsetAsync(psum, 0, (size_t)G * D * sizeof(float));
    cudaMemsetAsync(pmax, 0, (size_t)G * D * sizeof(int));
    cnt_kernel<<<(n + 255) / 256, 256>>>(batch, (int*)pcnt, n);
    x2h_kernel<<<(n * 64 + 255) / 256, 256>>>(x, x16, n * 64);
    wprep_kernel<<<192, 256>>>(W1, W2);

    // ---- layers ----
    const __half* cur = x16;
    __half* nxt = h16A;
    int mlpBlocks = (n + 127) / 128;
    int gthBlocks = (n * 32 + 255) / 256;

    for (int l = 0; l < 3; l++) {
        gather16_kernel<<<gthBlocks, 256>>>(cur, rowptr, csrsrc, z16, n, l > 0 ? 1 : 0);
        const unsigned* w1i = wt + (size_t)(l * 2 + 0) * WIMG;
        const unsigned* w2i = wt + (size_t)(l * 2 + 1) * WIMG;
        if (l < 2) {
            cudaMemsetAsync(stats, 0, 2 * D * sizeof(float));
            mlp16_kernel<<<mlpBlocks, 256, MLP_SMEM>>>(z16, w1i, w2i, b1 + l * D, b2 + l * D,
                nxt, stats, batch, (float*)psum, (int*)pmax, n, 0);
            bn_scale_kernel<<<1, D>>>(stats, bng + l * D, bnb + l * D, 1.f / (float)n);
            cur = nxt;
            nxt = (l == 0) ? h16B : h16A;
        } else {
            mlp16_kernel<<<mlpBlocks, 256, MLP_SMEM>>>(z16, w1i, w2i, b1 + l * D, b2 + l * D,
                nullptr, stats, batch, (float*)psum, (int*)pmax, n, 2);
        }
    }

    cudaMemsetAsync(d_out, 0, sizeof(float));
    final_kernel<<<G, 128>>>((const float*)psum, (const int*)pmax, (const int*)pcnt,
                             Wg, bg, pb, pm, y, (float*)d_out);
}